// round 8
// baseline (speedup 1.0000x reference)
#include <cuda_runtime.h>
#include <cuda_fp16.h>
#include <cstdint>

// ---------------------------------------------------------------------------
// Problem constants
// ---------------------------------------------------------------------------
#define BB    128
#define CIN   96
#define HH    63
#define WW    63
#define COUT  256
#define HO    30
#define WO    30
#define HID   24
#define TEMPR 31.0f

#define KDIM  2400          // Cin * 25
#define PDIM  900           // Ho * Wo
#define PPAD  1024

// GEMM tiling: CTA 128(M=cout) x 256(N=p), 8 warps at 64x64, fp16 inputs
#define KSTEP   32                      // fp16 elems per K-iter
#define NKIT    (KDIM / KSTEP)          // 75
#define MT      128
#define NT      256
#define STAGES  5
#define AROWU   20                      // row stride in u32 (16 data + 4 pad) = 80B
#define ATILE_U (MT * AROWU)            // 2560
#define BTILE_U (NT * AROWU)            // 5120
#define STAGE_U (ATILE_U + BTILE_U)     // 7680
#define SMEM_B  (STAGES * STAGE_U * 4)  // 153600 bytes

// im2col: block = (oh, quarter, b); stages 24ci x 5rows x 63cols slab
#define CIQ     24                      // channels per quarter
#define QK      (CIQ * 25)              // 600 fp16 per quarter
#define QK2     (QK / 2)                // 300 u32
#define SLABF   (CIQ * 5 * 64)          // 7680 floats

// ---------------------------------------------------------------------------
// Device scratch (wide alignment: viewed as u32 / 16B chunks)
// ---------------------------------------------------------------------------
__device__ float g_pooled[BB * CIN];
__device__ float g_att[BB * 2];
__device__ __align__(256) __half g_wh[(size_t)BB * COUT * KDIM];
__device__ __align__(256) __half g_xh[(size_t)BB * PPAD * KDIM];

// ---------------------------------------------------------------------------
// Helpers
// ---------------------------------------------------------------------------
__device__ __forceinline__ uint32_t smem_u32(const void* p) {
    uint32_t a;
    asm("{ .reg .u64 t; cvta.to.shared.u64 t, %1; cvt.u32.u64 %0, t; }"
        : "=r"(a) : "l"(p));
    return a;
}
__device__ __forceinline__ void cp16(uint32_t dst, const void* src) {
    asm volatile("cp.async.cg.shared.global [%0], [%1], 16;"
                 :: "r"(dst), "l"(src) : "memory");
}
__device__ __forceinline__ void cp_commit() {
    asm volatile("cp.async.commit_group;" ::: "memory");
}
__device__ __forceinline__ void cp_wait3() {
    asm volatile("cp.async.wait_group 3;" ::: "memory");
}
__device__ __forceinline__ void mma_f16(float* d, const uint32_t* a,
                                        const uint32_t* b) {
    asm volatile(
        "mma.sync.aligned.m16n8k16.row.col.f32.f16.f16.f32 "
        "{%0,%1,%2,%3}, {%4,%5,%6,%7}, {%8,%9}, {%0,%1,%2,%3};"
        : "+f"(d[0]), "+f"(d[1]), "+f"(d[2]), "+f"(d[3])
        : "r"(a[0]), "r"(a[1]), "r"(a[2]), "r"(a[3]), "r"(b[0]), "r"(b[1]));
}
__device__ __forceinline__ uint32_t pack_h2(float v0, float v1) {
    __half2 h;
    h.x = __float2half_rn(v0);
    h.y = __float2half_rn(v1);
    return *(uint32_t*)&h;
}

// ---------------------------------------------------------------------------
// Kernel 1: global average pool
// ---------------------------------------------------------------------------
__global__ void pool_kernel(const float* __restrict__ x) {
    const int ci = blockIdx.x;
    const int b  = blockIdx.y;
    const float* p = x + ((size_t)(b * CIN + ci)) * (HH * WW);
    float s = 0.f;
    for (int i = threadIdx.x; i < HH * WW; i += blockDim.x) s += p[i];
    __shared__ float red[32];
    #pragma unroll
    for (int o = 16; o; o >>= 1) s += __shfl_down_sync(0xffffffffu, s, o);
    if ((threadIdx.x & 31) == 0) red[threadIdx.x >> 5] = s;
    __syncthreads();
    if (threadIdx.x < 32) {
        s = (threadIdx.x < (blockDim.x >> 5)) ? red[threadIdx.x] : 0.f;
        #pragma unroll
        for (int o = 16; o; o >>= 1) s += __shfl_down_sync(0xffffffffu, s, o);
        if (threadIdx.x == 0) g_pooled[b * CIN + ci] = s * (1.0f / (HH * WW));
    }
}

// ---------------------------------------------------------------------------
// Kernel 2: attention MLP + softmax
// ---------------------------------------------------------------------------
__global__ void att_kernel(const float* __restrict__ w1,
                           const float* __restrict__ w2) {
    const int b = threadIdx.x;
    if (b >= BB) return;
    float pooled[CIN];
    #pragma unroll 8
    for (int i = 0; i < CIN; i++) pooled[i] = g_pooled[b * CIN + i];
    float l0 = 0.f, l1 = 0.f;
    for (int j = 0; j < HID; j++) {
        float h = 0.f;
        #pragma unroll 8
        for (int i = 0; i < CIN; i++) h += pooled[i] * w1[j * CIN + i];
        h = fmaxf(h, 0.f);
        l0 += h * w2[0 * HID + j];
        l1 += h * w2[1 * HID + j];
    }
    l0 *= (1.0f / TEMPR);
    l1 *= (1.0f / TEMPR);
    const float m  = fmaxf(l0, l1);
    const float e0 = __expf(l0 - m);
    const float e1 = __expf(l1 - m);
    const float inv = 1.0f / (e0 + e1);
    g_att[b * 2 + 0] = e0 * inv;
    g_att[b * 2 + 1] = e1 * inv;
}

// ---------------------------------------------------------------------------
// Kernel 3: mixed weight -> fp16
// ---------------------------------------------------------------------------
__global__ void wmix_kernel(const float* __restrict__ wc,
                            const float* __restrict__ we) {
    const int co = blockIdx.x;
    const int b  = blockIdx.y;
    const float a0 = g_att[2 * b], a1 = g_att[2 * b + 1];
    uint32_t* dst = (uint32_t*)(g_wh + ((size_t)b * COUT + co) * KDIM);
    const float* pc = wc + (size_t)co * KDIM;
    const float* pe = we + (size_t)co * KDIM;
    for (int k2 = threadIdx.x; k2 < KDIM / 2; k2 += blockDim.x) {
        const int k = k2 * 2;
        dst[k2] = pack_h2(a0 * pc[k] + a1 * pe[k],
                          a0 * pc[k + 1] + a1 * pe[k + 1]);
    }
}

// ---------------------------------------------------------------------------
// Kernel 4: im2col -> fp16.  Block = (oh, quarter, b).
// Stage 24ci x 5 rows x 63 cols slab; emit 30 ow x 300 u32 with int2 LUT,
// ow-outer loop (no divides in hot path).
// ---------------------------------------------------------------------------
__global__ void __launch_bounds__(256) im2col_kernel(const float* __restrict__ x) {
    __shared__ float slab[SLABF];       // 30720 B
    __shared__ int2  lut[QK2];          // 2400 B

    const int oh  = blockIdx.x;
    const int q   = blockIdx.y;
    const int b   = blockIdx.z;
    const int ci0 = q * CIQ;
    const int tid = threadIdx.x;
    const int wid = tid >> 5, lane = tid & 31;

    // build LUT: j2 -> slab offsets of fp16 pair (j, j+1), j = 2*j2
    for (int j2 = tid; j2 < QK2; j2 += 256) {
        int o[2];
        #pragma unroll
        for (int u = 0; u < 2; u++) {
            const int j  = j2 * 2 + u;
            const int cl = j / 25, t = j - cl * 25;
            const int kh = t / 5, kw = t - kh * 5;
            o[u] = (cl * 5 + kh) * 64 + kw;
        }
        lut[j2] = make_int2(o[0], o[1]);
    }

    // stage slab: 120 rows (cl,kh) x 63 cols
    const float* xb = x + ((size_t)b * CIN + ci0) * (HH * WW) + (size_t)(oh * 2) * WW;
    for (int row = wid; row < CIQ * 5; row += 8) {
        const int cl = row / 5, kh = row - cl * 5;
        const float* src = xb + (size_t)cl * (HH * WW) + kh * WW;
        float* dstr = slab + row * 64;
        if (lane < 63) dstr[lane] = src[lane];
        if (lane < 31) dstr[lane + 32] = src[lane + 32];
    }
    __syncthreads();

    // emit: u32 index within row = q*QK2 + j2 ; row stride = KDIM/2 u32
    uint32_t* dst0 = (uint32_t*)(g_xh + ((size_t)b * PPAD + oh * WO) * KDIM) + q * QK2;
    #pragma unroll 1
    for (int ow = 0; ow < WO; ow++) {
        const float* sl = slab + ow * 2;
        uint32_t* dr = dst0 + (size_t)ow * (KDIM / 2);
        for (int j2 = tid; j2 < QK2; j2 += 256) {
            const int2 o = lut[j2];
            dr[j2] = pack_h2(sl[o.x], sl[o.y]);
        }
    }
}

// ---------------------------------------------------------------------------
// Kernel 5: fp16 mma.sync GEMM (m16n8k16).  CTA = (b, co 128, p 256).
// 8 warps (2x4), warp tile 64x64.  5-stage cp.async, KSTEP=32.
// ---------------------------------------------------------------------------
__global__ void __launch_bounds__(256, 1)
gemm_kernel(const float* __restrict__ cb, const float* __restrict__ eb,
            float* __restrict__ out)
{
    extern __shared__ uint32_t sm[];
    const int b   = blockIdx.y;
    const int ct  = blockIdx.x >> 2;
    const int pt  = blockIdx.x & 3;
    const int co0 = ct * MT;
    const int p0  = pt * NT;

    const int tid  = threadIdx.x;
    const int wid  = tid >> 5;
    const int lane = tid & 31;
    const int wm   = wid & 1;
    const int wn   = wid >> 1;
    const int g    = lane >> 2;
    const int t    = lane & 3;

    const __half* gA = g_wh + ((size_t)b * COUT + co0) * KDIM;
    const __half* gB = g_xh + ((size_t)b * PPAD + p0) * KDIM;

    const uint32_t smbase = smem_u32(sm);
    const int ar0 = tid >> 2, as0 = tid & 3;
    const int ar1 = (tid + 256) >> 2;

    float acc[4][8][4];
    #pragma unroll
    for (int m = 0; m < 4; m++)
        #pragma unroll
        for (int n = 0; n < 8; n++)
            #pragma unroll
            for (int r = 0; r < 4; r++) acc[m][n][r] = 0.f;

    // ---- prologue ----
    #pragma unroll
    for (int s = 0; s < 3; s++) {
        const int k0 = s * KSTEP;
        const uint32_t ab = smbase + (uint32_t)(s * STAGE_U) * 4;
        const uint32_t bb = ab + ATILE_U * 4;
        cp16(ab + (uint32_t)(ar0 * AROWU + as0 * 4) * 4, gA + (size_t)ar0 * KDIM + k0 + as0 * 8);
        cp16(ab + (uint32_t)(ar1 * AROWU + as0 * 4) * 4, gA + (size_t)ar1 * KDIM + k0 + as0 * 8);
        #pragma unroll
        for (int j = 0; j < 4; j++) {
            const int c = tid + 256 * j;
            const int br = c >> 2, bs = c & 3;
            cp16(bb + (uint32_t)(br * AROWU + bs * 4) * 4, gB + (size_t)br * KDIM + k0 + bs * 8);
        }
        cp_commit();
    }

    // ---- main loop ----
    for (int it = 0; it < NKIT; it++) {
        if (it + 3 < NKIT) {
            const int s = (it + 3) % STAGES;
            const int k0 = (it + 3) * KSTEP;
            const uint32_t ab = smbase + (uint32_t)(s * STAGE_U) * 4;
            const uint32_t bb = ab + ATILE_U * 4;
            cp16(ab + (uint32_t)(ar0 * AROWU + as0 * 4) * 4, gA + (size_t)ar0 * KDIM + k0 + as0 * 8);
            cp16(ab + (uint32_t)(ar1 * AROWU + as0 * 4) * 4, gA + (size_t)ar1 * KDIM + k0 + as0 * 8);
            #pragma unroll
            for (int j = 0; j < 4; j++) {
                const int c = tid + 256 * j;
                const int br = c >> 2, bs = c & 3;
                cp16(bb + (uint32_t)(br * AROWU + bs * 4) * 4, gB + (size_t)br * KDIM + k0 + bs * 8);
            }
        }
        cp_commit();
        cp_wait3();
        __syncthreads();

        const uint32_t* As = sm + (it % STAGES) * STAGE_U;
        const uint32_t* Bs = As + ATILE_U;

        #pragma unroll
        for (int kk = 0; kk < 2; kk++) {
            const int c0 = kk * 8 + t;
            uint32_t afr[4][4];
            #pragma unroll
            for (int m = 0; m < 4; m++) {
                const int r = wm * 64 + m * 16 + g;
                afr[m][0] = As[r * AROWU + c0];
                afr[m][1] = As[(r + 8) * AROWU + c0];
                afr[m][2] = As[r * AROWU + c0 + 4];
                afr[m][3] = As[(r + 8) * AROWU + c0 + 4];
            }
            uint32_t bfr[8][2];
            #pragma unroll
            for (int n = 0; n < 8; n++) {
                const int col = wn * 64 + n * 8 + g;
                bfr[n][0] = Bs[col * AROWU + c0];
                bfr[n][1] = Bs[col * AROWU + c0 + 4];
            }
            #pragma unroll
            for (int m = 0; m < 4; m++)
                #pragma unroll
                for (int n = 0; n < 8; n++)
                    mma_f16(acc[m][n], afr[m], bfr[n]);
        }
        __syncthreads();
    }

    // ---- epilogue ----
    const float a0 = g_att[2 * b], a1 = g_att[2 * b + 1];
    #pragma unroll
    for (int m = 0; m < 4; m++) {
        const int co_lo = co0 + wm * 64 + m * 16 + g;
        const int co_hi = co_lo + 8;
        const float bias_lo = a0 * cb[co_lo] + a1 * eb[co_lo];
        const float bias_hi = a0 * cb[co_hi] + a1 * eb[co_hi];
        float* op_lo = out + ((size_t)b * COUT + co_lo) * PDIM;
        float* op_hi = out + ((size_t)b * COUT + co_hi) * PDIM;
        #pragma unroll
        for (int n = 0; n < 8; n++) {
            const int p = p0 + wn * 64 + n * 8 + t * 2;
            if (p < PDIM) {
                float2 v0 = make_float2(acc[m][n][0] + bias_lo, acc[m][n][1] + bias_lo);
                float2 v1 = make_float2(acc[m][n][2] + bias_hi, acc[m][n][3] + bias_hi);
                *(float2*)(op_lo + p) = v0;
                *(float2*)(op_hi + p) = v1;
            }
        }
    }
}

// ---------------------------------------------------------------------------
// Host launch
// ---------------------------------------------------------------------------
extern "C" void kernel_launch(void* const* d_in, const int* in_sizes, int n_in,
                              void* d_out, int out_size) {
    (void)in_sizes; (void)n_in; (void)out_size;
    const float* x  = (const float*)d_in[0];
    const float* wc = (const float*)d_in[1];
    const float* cb = (const float*)d_in[2];
    const float* we = (const float*)d_in[3];
    const float* eb = (const float*)d_in[4];
    const float* w1 = (const float*)d_in[5];
    const float* w2 = (const float*)d_in[6];
    float* out = (float*)d_out;

    static bool attr_set = false;
    if (!attr_set) {
        cudaFuncSetAttribute(gemm_kernel,
                             cudaFuncAttributeMaxDynamicSharedMemorySize, SMEM_B);
        attr_set = true;
    }

    pool_kernel<<<dim3(CIN, BB), 256>>>(x);
    att_kernel<<<1, 256>>>(w1, w2);
    wmix_kernel<<<dim3(COUT, BB), 256>>>(wc, we);
    im2col_kernel<<<dim3(HO, 4, BB), 256>>>(x);
    gemm_kernel<<<dim3(8, BB), 256, SMEM_B>>>(cb, eb, out);
}

// round 9
// speedup vs baseline: 1.0435x; 1.0435x over previous
#include <cuda_runtime.h>
#include <cuda_fp16.h>
#include <cstdint>

// ---------------------------------------------------------------------------
// Problem constants
// ---------------------------------------------------------------------------
#define BB    128
#define CIN   96
#define HH    63
#define WW    63
#define COUT  256
#define HO    30
#define WO    30
#define HID   24
#define TEMPR 31.0f

#define KDIM  2400          // Cin * 25
#define PDIM  900           // Ho * Wo
#define PPAD  1024

// GEMM tiling: CTA 128(M) x 256(N), 8 warps at 64x64, fp16, KSTEP=48
#define KSTEP   48                      // fp16 elems per K-iter
#define NKIT    (KDIM / KSTEP)          // 50
#define MT      128
#define NT      256
#define STAGES  4
#define AROWU   28                      // row stride in u32 (24 data + 4 pad) = 112B
#define ATILE_U (MT * AROWU)            // 3584
#define BTILE_U (NT * AROWU)            // 7168
#define STAGE_U (ATILE_U + BTILE_U)     // 10752
#define SMEM_B  (STAGES * STAGE_U * 4)  // 172032 bytes

// im2col: block = (oh, quarter, b); stages 24ci x 5rows x 63cols slab
#define CIQ     24
#define QK      (CIQ * 25)              // 600 fp16 per quarter
#define QK2     (QK / 2)                // 300 u32
#define QC4     (QK2 / 4)               // 75 16B chunks per ow
#define SLABF   (CIQ * 5 * 64)          // 7680 floats

// ---------------------------------------------------------------------------
// Device scratch (wide alignment: viewed as u32 / 16B chunks)
// ---------------------------------------------------------------------------
__device__ float g_pooled[BB * CIN];
__device__ float g_att[BB * 2];
__device__ __align__(256) __half g_wh[(size_t)BB * COUT * KDIM];
__device__ __align__(256) __half g_xh[(size_t)BB * PPAD * KDIM];

// ---------------------------------------------------------------------------
// Helpers
// ---------------------------------------------------------------------------
__device__ __forceinline__ uint32_t smem_u32(const void* p) {
    uint32_t a;
    asm("{ .reg .u64 t; cvta.to.shared.u64 t, %1; cvt.u32.u64 %0, t; }"
        : "=r"(a) : "l"(p));
    return a;
}
__device__ __forceinline__ void cp16(uint32_t dst, const void* src) {
    asm volatile("cp.async.cg.shared.global [%0], [%1], 16;"
                 :: "r"(dst), "l"(src) : "memory");
}
__device__ __forceinline__ void cp_commit() {
    asm volatile("cp.async.commit_group;" ::: "memory");
}
__device__ __forceinline__ void cp_wait3() {
    asm volatile("cp.async.wait_group 3;" ::: "memory");
}
__device__ __forceinline__ void mma_f16(float* d, const uint32_t* a,
                                        const uint32_t* b) {
    asm volatile(
        "mma.sync.aligned.m16n8k16.row.col.f32.f16.f16.f32 "
        "{%0,%1,%2,%3}, {%4,%5,%6,%7}, {%8,%9}, {%0,%1,%2,%3};"
        : "+f"(d[0]), "+f"(d[1]), "+f"(d[2]), "+f"(d[3])
        : "r"(a[0]), "r"(a[1]), "r"(a[2]), "r"(a[3]), "r"(b[0]), "r"(b[1]));
}
__device__ __forceinline__ uint32_t pack_h2(float v0, float v1) {
    __half2 h;
    h.x = __float2half_rn(v0);
    h.y = __float2half_rn(v1);
    return *(uint32_t*)&h;
}

// ---------------------------------------------------------------------------
// Kernel 1: global average pool
// ---------------------------------------------------------------------------
__global__ void pool_kernel(const float* __restrict__ x) {
    const int ci = blockIdx.x;
    const int b  = blockIdx.y;
    const float* p = x + ((size_t)(b * CIN + ci)) * (HH * WW);
    float s = 0.f;
    for (int i = threadIdx.x; i < HH * WW; i += blockDim.x) s += p[i];
    __shared__ float red[32];
    #pragma unroll
    for (int o = 16; o; o >>= 1) s += __shfl_down_sync(0xffffffffu, s, o);
    if ((threadIdx.x & 31) == 0) red[threadIdx.x >> 5] = s;
    __syncthreads();
    if (threadIdx.x < 32) {
        s = (threadIdx.x < (blockDim.x >> 5)) ? red[threadIdx.x] : 0.f;
        #pragma unroll
        for (int o = 16; o; o >>= 1) s += __shfl_down_sync(0xffffffffu, s, o);
        if (threadIdx.x == 0) g_pooled[b * CIN + ci] = s * (1.0f / (HH * WW));
    }
}

// ---------------------------------------------------------------------------
// Kernel 2: attention MLP + softmax
// ---------------------------------------------------------------------------
__global__ void att_kernel(const float* __restrict__ w1,
                           const float* __restrict__ w2) {
    const int b = threadIdx.x;
    if (b >= BB) return;
    float pooled[CIN];
    #pragma unroll 8
    for (int i = 0; i < CIN; i++) pooled[i] = g_pooled[b * CIN + i];
    float l0 = 0.f, l1 = 0.f;
    for (int j = 0; j < HID; j++) {
        float h = 0.f;
        #pragma unroll 8
        for (int i = 0; i < CIN; i++) h += pooled[i] * w1[j * CIN + i];
        h = fmaxf(h, 0.f);
        l0 += h * w2[0 * HID + j];
        l1 += h * w2[1 * HID + j];
    }
    l0 *= (1.0f / TEMPR);
    l1 *= (1.0f / TEMPR);
    const float m  = fmaxf(l0, l1);
    const float e0 = __expf(l0 - m);
    const float e1 = __expf(l1 - m);
    const float inv = 1.0f / (e0 + e1);
    g_att[b * 2 + 0] = e0 * inv;
    g_att[b * 2 + 1] = e1 * inv;
}

// ---------------------------------------------------------------------------
// Kernel 3: mixed weight -> fp16
// ---------------------------------------------------------------------------
__global__ void wmix_kernel(const float* __restrict__ wc,
                            const float* __restrict__ we) {
    const int co = blockIdx.x;
    const int b  = blockIdx.y;
    const float a0 = g_att[2 * b], a1 = g_att[2 * b + 1];
    uint32_t* dst = (uint32_t*)(g_wh + ((size_t)b * COUT + co) * KDIM);
    const float* pc = wc + (size_t)co * KDIM;
    const float* pe = we + (size_t)co * KDIM;
    for (int k2 = threadIdx.x; k2 < KDIM / 2; k2 += blockDim.x) {
        const int k = k2 * 2;
        dst[k2] = pack_h2(a0 * pc[k] + a1 * pe[k],
                          a0 * pc[k + 1] + a1 * pe[k + 1]);
    }
}

// ---------------------------------------------------------------------------
// Kernel 4: im2col -> fp16.  Block = (oh, quarter, b).
// Stage 24ci x 5 rows x 63 cols slab; emit flattened 30ow x 75 chunks,
// each thread-iter: 2 LDS.128 (offset LUT) + 8 slab reads -> 1 STG.128.
// ---------------------------------------------------------------------------
__global__ void __launch_bounds__(256) im2col_kernel(const float* __restrict__ x) {
    __shared__ float slab[SLABF];                  // 30720 B
    __shared__ __align__(16) int soff[QK];         // 2400 B

    const int oh  = blockIdx.x;
    const int q   = blockIdx.y;
    const int b   = blockIdx.z;
    const int ci0 = q * CIQ;
    const int tid = threadIdx.x;
    const int wid = tid >> 5, lane = tid & 31;

    // build offset LUT: j -> slab index of k-position j (within quarter)
    for (int j = tid; j < QK; j += 256) {
        const int cl = j / 25, t = j - cl * 25;
        const int kh = t / 5, kw = t - kh * 5;
        soff[j] = (cl * 5 + kh) * 64 + kw;
    }

    // stage slab: 120 rows (cl,kh) x 63 cols
    const float* xb = x + ((size_t)b * CIN + ci0) * (HH * WW) + (size_t)(oh * 2) * WW;
    for (int row = wid; row < CIQ * 5; row += 8) {
        const int cl = row / 5, kh = row - cl * 5;
        const float* src = xb + (size_t)cl * (HH * WW) + kh * WW;
        float* dstr = slab + row * 64;
        if (lane < 63) dstr[lane] = src[lane];
        if (lane < 31) dstr[lane + 32] = src[lane + 32];
    }
    __syncthreads();

    // emit: 2250 16B-chunks; ow = idx/75 (const mul), chunk c4 = idx%75
    uint32_t* dst0 = (uint32_t*)(g_xh + ((size_t)b * PPAD + oh * WO) * KDIM) + q * QK2;
    for (int idx = tid; idx < WO * QC4; idx += 256) {
        const int ow = idx / QC4;
        const int c4 = idx - ow * QC4;
        const int4 o0 = *(const int4*)&soff[c4 * 8];
        const int4 o1 = *(const int4*)&soff[c4 * 8 + 4];
        const float* sl = slab + ow * 2;
        uint4 v;
        v.x = pack_h2(sl[o0.x], sl[o0.y]);
        v.y = pack_h2(sl[o0.z], sl[o0.w]);
        v.z = pack_h2(sl[o1.x], sl[o1.y]);
        v.w = pack_h2(sl[o1.z], sl[o1.w]);
        *(uint4*)&dst0[(size_t)ow * (KDIM / 2) + c4 * 4] = v;
    }
}

// ---------------------------------------------------------------------------
// Kernel 5: fp16 mma.sync GEMM (m16n8k16).  CTA = (b, co 128, p 256).
// 8 warps (2x4), warp tile 64x64.  4-stage cp.async, KSTEP=48.
// ---------------------------------------------------------------------------
__global__ void __launch_bounds__(256, 1)
gemm_kernel(const float* __restrict__ cb, const float* __restrict__ eb,
            float* __restrict__ out)
{
    extern __shared__ uint32_t sm[];
    const int b   = blockIdx.y;
    const int ct  = blockIdx.x >> 2;
    const int pt  = blockIdx.x & 3;
    const int co0 = ct * MT;
    const int p0  = pt * NT;

    const int tid  = threadIdx.x;
    const int wid  = tid >> 5;
    const int lane = tid & 31;
    const int wm   = wid & 1;
    const int wn   = wid >> 1;
    const int g    = lane >> 2;
    const int t    = lane & 3;

    const __half* gA = g_wh + ((size_t)b * COUT + co0) * KDIM;
    const __half* gB = g_xh + ((size_t)b * PPAD + p0) * KDIM;

    const uint32_t smbase = smem_u32(sm);

    float acc[4][8][4];
    #pragma unroll
    for (int m = 0; m < 4; m++)
        #pragma unroll
        for (int n = 0; n < 8; n++)
            #pragma unroll
            for (int r = 0; r < 4; r++) acc[m][n][r] = 0.f;

    // staging: A = 128 rows x 6 chunks = 768; B = 256 x 6 = 1536
    // ---- prologue: stages 0..2 ----
    #pragma unroll
    for (int s = 0; s < 3; s++) {
        const int k0 = s * KSTEP;
        const uint32_t ab = smbase + (uint32_t)(s * STAGE_U) * 4;
        const uint32_t bb = ab + ATILE_U * 4;
        #pragma unroll
        for (int j = 0; j < 3; j++) {
            const int c = tid + 256 * j;
            const int r = c / 6, sg = c - r * 6;
            cp16(ab + (uint32_t)(r * AROWU + sg * 4) * 4, gA + (size_t)r * KDIM + k0 + sg * 8);
        }
        #pragma unroll
        for (int j = 0; j < 6; j++) {
            const int c = tid + 256 * j;
            const int r = c / 6, sg = c - r * 6;
            cp16(bb + (uint32_t)(r * AROWU + sg * 4) * 4, gB + (size_t)r * KDIM + k0 + sg * 8);
        }
        cp_commit();
    }

    // ---- main loop ----
    for (int it = 0; it < NKIT; it++) {
        if (it + 3 < NKIT) {
            const int s = (it + 3) & 3;
            const int k0 = (it + 3) * KSTEP;
            const uint32_t ab = smbase + (uint32_t)(s * STAGE_U) * 4;
            const uint32_t bb = ab + ATILE_U * 4;
            #pragma unroll
            for (int j = 0; j < 3; j++) {
                const int c = tid + 256 * j;
                const int r = c / 6, sg = c - r * 6;
                cp16(ab + (uint32_t)(r * AROWU + sg * 4) * 4, gA + (size_t)r * KDIM + k0 + sg * 8);
            }
            #pragma unroll
            for (int j = 0; j < 6; j++) {
                const int c = tid + 256 * j;
                const int r = c / 6, sg = c - r * 6;
                cp16(bb + (uint32_t)(r * AROWU + sg * 4) * 4, gB + (size_t)r * KDIM + k0 + sg * 8);
            }
        }
        cp_commit();
        cp_wait3();
        __syncthreads();

        const uint32_t* As = sm + (it & 3) * STAGE_U;
        const uint32_t* Bs = As + ATILE_U;

        #pragma unroll
        for (int kk = 0; kk < 3; kk++) {
            const int c0 = kk * 8 + t;
            uint32_t afr[4][4];
            #pragma unroll
            for (int m = 0; m < 4; m++) {
                const int r = wm * 64 + m * 16 + g;
                afr[m][0] = As[r * AROWU + c0];
                afr[m][1] = As[(r + 8) * AROWU + c0];
                afr[m][2] = As[r * AROWU + c0 + 4];
                afr[m][3] = As[(r + 8) * AROWU + c0 + 4];
            }
            uint32_t bfr[8][2];
            #pragma unroll
            for (int n = 0; n < 8; n++) {
                const int col = wn * 64 + n * 8 + g;
                bfr[n][0] = Bs[col * AROWU + c0];
                bfr[n][1] = Bs[col * AROWU + c0 + 4];
            }
            #pragma unroll
            for (int m = 0; m < 4; m++)
                #pragma unroll
                for (int n = 0; n < 8; n++)
                    mma_f16(acc[m][n], afr[m], bfr[n]);
        }
        __syncthreads();
    }

    // ---- epilogue ----
    const float a0 = g_att[2 * b], a1 = g_att[2 * b + 1];
    #pragma unroll
    for (int m = 0; m < 4; m++) {
        const int co_lo = co0 + wm * 64 + m * 16 + g;
        const int co_hi = co_lo + 8;
        const float bias_lo = a0 * cb[co_lo] + a1 * eb[co_lo];
        const float bias_hi = a0 * cb[co_hi] + a1 * eb[co_hi];
        float* op_lo = out + ((size_t)b * COUT + co_lo) * PDIM;
        float* op_hi = out + ((size_t)b * COUT + co_hi) * PDIM;
        #pragma unroll
        for (int n = 0; n < 8; n++) {
            const int p = p0 + wn * 64 + n * 8 + t * 2;
            if (p < PDIM) {
                float2 v0 = make_float2(acc[m][n][0] + bias_lo, acc[m][n][1] + bias_lo);
                float2 v1 = make_float2(acc[m][n][2] + bias_hi, acc[m][n][3] + bias_hi);
                *(float2*)(op_lo + p) = v0;
                *(float2*)(op_hi + p) = v1;
            }
        }
    }
}

// ---------------------------------------------------------------------------
// Host launch
// ---------------------------------------------------------------------------
extern "C" void kernel_launch(void* const* d_in, const int* in_sizes, int n_in,
                              void* d_out, int out_size) {
    (void)in_sizes; (void)n_in; (void)out_size;
    const float* x  = (const float*)d_in[0];
    const float* wc = (const float*)d_in[1];
    const float* cb = (const float*)d_in[2];
    const float* we = (const float*)d_in[3];
    const float* eb = (const float*)d_in[4];
    const float* w1 = (const float*)d_in[5];
    const float* w2 = (const float*)d_in[6];
    float* out = (float*)d_out;

    static bool attr_set = false;
    if (!attr_set) {
        cudaFuncSetAttribute(gemm_kernel,
                             cudaFuncAttributeMaxDynamicSharedMemorySize, SMEM_B);
        attr_set = true;
    }

    pool_kernel<<<dim3(CIN, BB), 256>>>(x);
    att_kernel<<<1, 256>>>(w1, w2);
    wmix_kernel<<<dim3(COUT, BB), 256>>>(wc, we);
    im2col_kernel<<<dim3(HO, 4, BB), 256>>>(x);
    gemm_kernel<<<dim3(8, BB), 256, SMEM_B>>>(cb, eb, out);
}

// round 10
// speedup vs baseline: 1.0465x; 1.0029x over previous
#include <cuda_runtime.h>
#include <cuda_fp16.h>
#include <cstdint>

// ---------------------------------------------------------------------------
// Problem constants
// ---------------------------------------------------------------------------
#define BB    128
#define CIN   96
#define HH    63
#define WW    63
#define COUT  256
#define HO    30
#define WO    30
#define HID   24
#define TEMPR 31.0f

#define KDIM  2400          // Cin * 25
#define PDIM  900           // Ho * Wo
#define PPAD  1024

// GEMM tiling: CTA 128(M) x 256(N), 8 warps at 64x64, fp16, KSTEP=48
#define KSTEP   48
#define NKIT    (KDIM / KSTEP)          // 50
#define MT      128
#define NT      256
#define STAGES  4
#define AROWU   28                      // row stride in u32 = 112B (LDSM conflict-free)
#define ATILE_U (MT * AROWU)            // 3584
#define BTILE_U (NT * AROWU)            // 7168
#define STAGE_U (ATILE_U + BTILE_U)     // 10752
#define SMEM_B  (STAGES * STAGE_U * 4)  // 172032 bytes

// im2col: block = (oh, quarter, b); stages 24ci x 5rows x 63cols slab
#define CIQ     24
#define QK      (CIQ * 25)              // 600 fp16 per quarter
#define QK2     (QK / 2)                // 300 u32
#define QC4     (QK2 / 4)               // 75 16B chunks per ow
#define SLABF   (CIQ * 5 * 64)          // 7680 floats

// ---------------------------------------------------------------------------
// Device scratch
// ---------------------------------------------------------------------------
__device__ float g_pooled[BB * CIN];
__device__ float g_att[BB * 2];
__device__ __align__(256) __half g_wh[(size_t)BB * COUT * KDIM];
__device__ __align__(256) __half g_xh[(size_t)BB * PPAD * KDIM];

// ---------------------------------------------------------------------------
// Helpers
// ---------------------------------------------------------------------------
__device__ __forceinline__ uint32_t smem_u32(const void* p) {
    uint32_t a;
    asm("{ .reg .u64 t; cvta.to.shared.u64 t, %1; cvt.u32.u64 %0, t; }"
        : "=r"(a) : "l"(p));
    return a;
}
__device__ __forceinline__ void cp16(uint32_t dst, const void* src) {
    asm volatile("cp.async.cg.shared.global [%0], [%1], 16;"
                 :: "r"(dst), "l"(src) : "memory");
}
__device__ __forceinline__ void cp_commit() {
    asm volatile("cp.async.commit_group;" ::: "memory");
}
__device__ __forceinline__ void cp_wait3() {
    asm volatile("cp.async.wait_group 3;" ::: "memory");
}
__device__ __forceinline__ void ldsm4(uint32_t* r, uint32_t addr) {
    asm volatile("ldmatrix.sync.aligned.m8n8.x4.shared.b16 {%0,%1,%2,%3}, [%4];"
                 : "=r"(r[0]), "=r"(r[1]), "=r"(r[2]), "=r"(r[3]) : "r"(addr));
}
__device__ __forceinline__ void mma_f16(float* d, const uint32_t* a,
                                        const uint32_t* b) {
    asm volatile(
        "mma.sync.aligned.m16n8k16.row.col.f32.f16.f16.f32 "
        "{%0,%1,%2,%3}, {%4,%5,%6,%7}, {%8,%9}, {%0,%1,%2,%3};"
        : "+f"(d[0]), "+f"(d[1]), "+f"(d[2]), "+f"(d[3])
        : "r"(a[0]), "r"(a[1]), "r"(a[2]), "r"(a[3]), "r"(b[0]), "r"(b[1]));
}
__device__ __forceinline__ uint32_t pack_h2(float v0, float v1) {
    __half2 h;
    h.x = __float2half_rn(v0);
    h.y = __float2half_rn(v1);
    return *(uint32_t*)&h;
}

// ---------------------------------------------------------------------------
// Kernel 1: global average pool
// ---------------------------------------------------------------------------
__global__ void pool_kernel(const float* __restrict__ x) {
    const int ci = blockIdx.x;
    const int b  = blockIdx.y;
    const float* p = x + ((size_t)(b * CIN + ci)) * (HH * WW);
    float s = 0.f;
    for (int i = threadIdx.x; i < HH * WW; i += blockDim.x) s += p[i];
    __shared__ float red[32];
    #pragma unroll
    for (int o = 16; o; o >>= 1) s += __shfl_down_sync(0xffffffffu, s, o);
    if ((threadIdx.x & 31) == 0) red[threadIdx.x >> 5] = s;
    __syncthreads();
    if (threadIdx.x < 32) {
        s = (threadIdx.x < (blockDim.x >> 5)) ? red[threadIdx.x] : 0.f;
        #pragma unroll
        for (int o = 16; o; o >>= 1) s += __shfl_down_sync(0xffffffffu, s, o);
        if (threadIdx.x == 0) g_pooled[b * CIN + ci] = s * (1.0f / (HH * WW));
    }
}

// ---------------------------------------------------------------------------
// Kernel 2: attention MLP + softmax
// ---------------------------------------------------------------------------
__global__ void att_kernel(const float* __restrict__ w1,
                           const float* __restrict__ w2) {
    const int b = threadIdx.x;
    if (b >= BB) return;
    float pooled[CIN];
    #pragma unroll 8
    for (int i = 0; i < CIN; i++) pooled[i] = g_pooled[b * CIN + i];
    float l0 = 0.f, l1 = 0.f;
    for (int j = 0; j < HID; j++) {
        float h = 0.f;
        #pragma unroll 8
        for (int i = 0; i < CIN; i++) h += pooled[i] * w1[j * CIN + i];
        h = fmaxf(h, 0.f);
        l0 += h * w2[0 * HID + j];
        l1 += h * w2[1 * HID + j];
    }
    l0 *= (1.0f / TEMPR);
    l1 *= (1.0f / TEMPR);
    const float m  = fmaxf(l0, l1);
    const float e0 = __expf(l0 - m);
    const float e1 = __expf(l1 - m);
    const float inv = 1.0f / (e0 + e1);
    g_att[b * 2 + 0] = e0 * inv;
    g_att[b * 2 + 1] = e1 * inv;
}

// ---------------------------------------------------------------------------
// Kernel 3: mixed weight -> fp16
// ---------------------------------------------------------------------------
__global__ void wmix_kernel(const float* __restrict__ wc,
                            const float* __restrict__ we) {
    const int co = blockIdx.x;
    const int b  = blockIdx.y;
    const float a0 = g_att[2 * b], a1 = g_att[2 * b + 1];
    uint32_t* dst = (uint32_t*)(g_wh + ((size_t)b * COUT + co) * KDIM);
    const float* pc = wc + (size_t)co * KDIM;
    const float* pe = we + (size_t)co * KDIM;
    for (int k2 = threadIdx.x; k2 < KDIM / 2; k2 += blockDim.x) {
        const int k = k2 * 2;
        dst[k2] = pack_h2(a0 * pc[k] + a1 * pe[k],
                          a0 * pc[k + 1] + a1 * pe[k + 1]);
    }
}

// ---------------------------------------------------------------------------
// Kernel 4: im2col -> fp16.  Block = (oh, quarter, b).
// ---------------------------------------------------------------------------
__global__ void __launch_bounds__(256) im2col_kernel(const float* __restrict__ x) {
    __shared__ float slab[SLABF];
    __shared__ __align__(16) int soff[QK];

    const int oh  = blockIdx.x;
    const int q   = blockIdx.y;
    const int b   = blockIdx.z;
    const int ci0 = q * CIQ;
    const int tid = threadIdx.x;
    const int wid = tid >> 5, lane = tid & 31;

    for (int j = tid; j < QK; j += 256) {
        const int cl = j / 25, t = j - cl * 25;
        const int kh = t / 5, kw = t - kh * 5;
        soff[j] = (cl * 5 + kh) * 64 + kw;
    }

    const float* xb = x + ((size_t)b * CIN + ci0) * (HH * WW) + (size_t)(oh * 2) * WW;
    for (int row = wid; row < CIQ * 5; row += 8) {
        const int cl = row / 5, kh = row - cl * 5;
        const float* src = xb + (size_t)cl * (HH * WW) + kh * WW;
        float* dstr = slab + row * 64;
        if (lane < 63) dstr[lane] = src[lane];
        if (lane < 31) dstr[lane + 32] = src[lane + 32];
    }
    __syncthreads();

    uint32_t* dst0 = (uint32_t*)(g_xh + ((size_t)b * PPAD + oh * WO) * KDIM) + q * QK2;
    for (int idx = tid; idx < WO * QC4; idx += 256) {
        const int ow = idx / QC4;
        const int c4 = idx - ow * QC4;
        const int4 o0 = *(const int4*)&soff[c4 * 8];
        const int4 o1 = *(const int4*)&soff[c4 * 8 + 4];
        const float* sl = slab + ow * 2;
        uint4 v;
        v.x = pack_h2(sl[o0.x], sl[o0.y]);
        v.y = pack_h2(sl[o0.z], sl[o0.w]);
        v.z = pack_h2(sl[o1.x], sl[o1.y]);
        v.w = pack_h2(sl[o1.z], sl[o1.w]);
        *(uint4*)&dst0[(size_t)ow * (KDIM / 2) + c4 * 4] = v;
    }
}

// ---------------------------------------------------------------------------
// Kernel 5: fp16 mma.sync GEMM with ldmatrix fragment loads.
// CTA = (b, co 128, p 256).  8 warps (2x4), warp tile 64x64.
// 4-stage cp.async, KSTEP=48; 24 LDSM.x4 + 96 MMA per warp-iter.
// ---------------------------------------------------------------------------
__global__ void __launch_bounds__(256, 1)
gemm_kernel(const float* __restrict__ cb, const float* __restrict__ eb,
            float* __restrict__ out)
{
    extern __shared__ uint32_t sm[];
    const int b   = blockIdx.y;
    const int ct  = blockIdx.x >> 2;
    const int pt  = blockIdx.x & 3;
    const int co0 = ct * MT;
    const int p0  = pt * NT;

    const int tid  = threadIdx.x;
    const int wid  = tid >> 5;
    const int lane = tid & 31;
    const int wm   = wid & 1;
    const int wn   = wid >> 1;
    const int g    = lane >> 2;
    const int t    = lane & 3;

    const __half* gA = g_wh + ((size_t)b * COUT + co0) * KDIM;
    const __half* gB = g_xh + ((size_t)b * PPAD + p0) * KDIM;

    const uint32_t smbase = smem_u32(sm);

    // ldmatrix per-lane base offsets (bytes, within a stage)
    // A tile m: groups: lanes 0-7 rows r0..r0+7 half0; 8-15 rows+8 half0;
    //           16-23 rows r0..r0+7 half1; 24-31 rows+8 half1
    uint32_t aoff[4];
    #pragma unroll
    for (int m = 0; m < 4; m++) {
        const int row = wm * 64 + m * 16 + (lane & 15);
        aoff[m] = (uint32_t)(row * AROWU + (lane >> 4) * 4) * 4;
    }
    // B x4 #j covers n-frags 2j, 2j+1:
    //  lanes 0-7: ngrp 2j rows, half0 ; 8-15: ngrp 2j, half1
    //  lanes 16-23: ngrp 2j+1, half0 ; 24-31: ngrp 2j+1, half1
    uint32_t boff[4];
    #pragma unroll
    for (int j = 0; j < 4; j++) {
        const int row = wn * 64 + j * 16 + ((lane >> 4) << 3) + (lane & 7);
        boff[j] = (uint32_t)(ATILE_U + row * AROWU + ((lane >> 3) & 1) * 4) * 4;
    }

    float acc[4][8][4];
    #pragma unroll
    for (int m = 0; m < 4; m++)
        #pragma unroll
        for (int n = 0; n < 8; n++)
            #pragma unroll
            for (int r = 0; r < 4; r++) acc[m][n][r] = 0.f;

    // ---- prologue: stages 0..2 ----
    #pragma unroll
    for (int s = 0; s < 3; s++) {
        const int k0 = s * KSTEP;
        const uint32_t ab = smbase + (uint32_t)(s * STAGE_U) * 4;
        const uint32_t bb = ab + ATILE_U * 4;
        #pragma unroll
        for (int j = 0; j < 3; j++) {
            const int c = tid + 256 * j;
            const int r = c / 6, sg = c - r * 6;
            cp16(ab + (uint32_t)(r * AROWU + sg * 4) * 4, gA + (size_t)r * KDIM + k0 + sg * 8);
        }
        #pragma unroll
        for (int j = 0; j < 6; j++) {
            const int c = tid + 256 * j;
            const int r = c / 6, sg = c - r * 6;
            cp16(bb + (uint32_t)(r * AROWU + sg * 4) * 4, gB + (size_t)r * KDIM + k0 + sg * 8);
        }
        cp_commit();
    }

    // ---- main loop ----
    for (int it = 0; it < NKIT; it++) {
        if (it + 3 < NKIT) {
            const int s = (it + 3) & 3;
            const int k0 = (it + 3) * KSTEP;
            const uint32_t ab = smbase + (uint32_t)(s * STAGE_U) * 4;
            const uint32_t bb = ab + ATILE_U * 4;
            #pragma unroll
            for (int j = 0; j < 3; j++) {
                const int c = tid + 256 * j;
                const int r = c / 6, sg = c - r * 6;
                cp16(ab + (uint32_t)(r * AROWU + sg * 4) * 4, gA + (size_t)r * KDIM + k0 + sg * 8);
            }
            #pragma unroll
            for (int j = 0; j < 6; j++) {
                const int c = tid + 256 * j;
                const int r = c / 6, sg = c - r * 6;
                cp16(bb + (uint32_t)(r * AROWU + sg * 4) * 4, gB + (size_t)r * KDIM + k0 + sg * 8);
            }
        }
        cp_commit();
        cp_wait3();
        __syncthreads();

        const uint32_t stoff = smbase + (uint32_t)((it & 3) * STAGE_U) * 4;

        #pragma unroll
        for (int kk = 0; kk < 3; kk++) {
            const uint32_t kb = stoff + kk * 32;   // +8 u32 per kk
            uint32_t afr[4][4];
            #pragma unroll
            for (int m = 0; m < 4; m++)
                ldsm4(afr[m], kb + aoff[m]);
            uint32_t bfr[8][2];
            #pragma unroll
            for (int j = 0; j < 4; j++) {
                uint32_t r[4];
                ldsm4(r, kb + boff[j]);
                bfr[2 * j][0] = r[0]; bfr[2 * j][1] = r[1];
                bfr[2 * j + 1][0] = r[2]; bfr[2 * j + 1][1] = r[3];
            }
            #pragma unroll
            for (int m = 0; m < 4; m++)
                #pragma unroll
                for (int n = 0; n < 8; n++)
                    mma_f16(acc[m][n], afr[m], bfr[n]);
        }
        __syncthreads();
    }

    // ---- epilogue ----
    const float a0 = g_att[2 * b], a1 = g_att[2 * b + 1];
    #pragma unroll
    for (int m = 0; m < 4; m++) {
        const int co_lo = co0 + wm * 64 + m * 16 + g;
        const int co_hi = co_lo + 8;
        const float bias_lo = a0 * cb[co_lo] + a1 * eb[co_lo];
        const float bias_hi = a0 * cb[co_hi] + a1 * eb[co_hi];
        float* op_lo = out + ((size_t)b * COUT + co_lo) * PDIM;
        float* op_hi = out + ((size_t)b * COUT + co_hi) * PDIM;
        #pragma unroll
        for (int n = 0; n < 8; n++) {
            const int p = p0 + wn * 64 + n * 8 + t * 2;
            if (p < PDIM) {
                float2 v0 = make_float2(acc[m][n][0] + bias_lo, acc[m][n][1] + bias_lo);
                float2 v1 = make_float2(acc[m][n][2] + bias_hi, acc[m][n][3] + bias_hi);
                *(float2*)(op_lo + p) = v0;
                *(float2*)(op_hi + p) = v1;
            }
        }
    }
}

// ---------------------------------------------------------------------------
// Host launch
// ---------------------------------------------------------------------------
extern "C" void kernel_launch(void* const* d_in, const int* in_sizes, int n_in,
                              void* d_out, int out_size) {
    (void)in_sizes; (void)n_in; (void)out_size;
    const float* x  = (const float*)d_in[0];
    const float* wc = (const float*)d_in[1];
    const float* cb = (const float*)d_in[2];
    const float* we = (const float*)d_in[3];
    const float* eb = (const float*)d_in[4];
    const float* w1 = (const float*)d_in[5];
    const float* w2 = (const float*)d_in[6];
    float* out = (float*)d_out;

    static bool attr_set = false;
    if (!attr_set) {
        cudaFuncSetAttribute(gemm_kernel,
                             cudaFuncAttributeMaxDynamicSharedMemorySize, SMEM_B);
        attr_set = true;
    }

    pool_kernel<<<dim3(CIN, BB), 256>>>(x);
    att_kernel<<<1, 256>>>(w1, w2);
    wmix_kernel<<<dim3(COUT, BB), 256>>>(wc, we);
    im2col_kernel<<<dim3(HO, 4, BB), 256>>>(x);
    gemm_kernel<<<dim3(8, BB), 256, SMEM_B>>>(cb, eb, out);
}

// round 11
// speedup vs baseline: 1.0876x; 1.0393x over previous
#include <cuda_runtime.h>
#include <cuda_fp16.h>
#include <cstdint>

// ---------------------------------------------------------------------------
// Problem constants
// ---------------------------------------------------------------------------
#define BB    128
#define CIN   96
#define HH    63
#define WW    63
#define COUT  256
#define HO    30
#define WO    30
#define HID   24
#define TEMPR 31.0f

#define KDIM  2400          // Cin * 25
#define PDIM  900           // Ho * Wo
#define PPAD  1024

// GEMM tiling: CTA 128(M) x 96(N), 8 warps at 64x24, fp16, KSTEP=48
#define KSTEP   48
#define NKIT    (KDIM / KSTEP)          // 50
#define MT      128
#define NT      96
#define NPT     10                      // p-tiles: 10 * 96 = 960
#define STAGES  4
#define AROWU   28                      // row stride in u32 = 112B
#define ATILE_U (MT * AROWU)            // 3584
#define BTILE_U (NT * AROWU)            // 2688
#define STAGE_U (ATILE_U + BTILE_U)     // 6272
#define SMEM_B  (STAGES * STAGE_U * 4)  // 100352 bytes -> 2 CTAs/SM
#define BCHUNKS (NT * 6)                // 576 cp.async chunks for B

// im2col: block = (oh, quarter, b); slab row stride 65 (bank-conflict fix)
#define CIQ     24
#define QK      (CIQ * 25)              // 600 fp16 per quarter
#define QK2     (QK / 2)                // 300 u32
#define QC4     (QK2 / 4)               // 75 16B chunks per ow
#define SROW    65
#define SLABF   (CIQ * 5 * SROW)        // 7800 floats

// ---------------------------------------------------------------------------
// Device scratch
// ---------------------------------------------------------------------------
__device__ float g_pooled[BB * CIN];
__device__ float g_att[BB * 2];
__device__ __align__(256) __half g_wh[(size_t)BB * COUT * KDIM];
__device__ __align__(256) __half g_xh[(size_t)BB * PPAD * KDIM];

// ---------------------------------------------------------------------------
// Helpers
// ---------------------------------------------------------------------------
__device__ __forceinline__ uint32_t smem_u32(const void* p) {
    uint32_t a;
    asm("{ .reg .u64 t; cvta.to.shared.u64 t, %1; cvt.u32.u64 %0, t; }"
        : "=r"(a) : "l"(p));
    return a;
}
__device__ __forceinline__ void cp16(uint32_t dst, const void* src) {
    asm volatile("cp.async.cg.shared.global [%0], [%1], 16;"
                 :: "r"(dst), "l"(src) : "memory");
}
__device__ __forceinline__ void cp_commit() {
    asm volatile("cp.async.commit_group;" ::: "memory");
}
__device__ __forceinline__ void cp_wait3() {
    asm volatile("cp.async.wait_group 3;" ::: "memory");
}
__device__ __forceinline__ void ldsm4(uint32_t* r, uint32_t addr) {
    asm volatile("ldmatrix.sync.aligned.m8n8.x4.shared.b16 {%0,%1,%2,%3}, [%4];"
                 : "=r"(r[0]), "=r"(r[1]), "=r"(r[2]), "=r"(r[3]) : "r"(addr));
}
__device__ __forceinline__ void ldsm2(uint32_t* r, uint32_t addr) {
    asm volatile("ldmatrix.sync.aligned.m8n8.x2.shared.b16 {%0,%1}, [%2];"
                 : "=r"(r[0]), "=r"(r[1]) : "r"(addr));
}
__device__ __forceinline__ void mma_f16(float* d, const uint32_t* a,
                                        const uint32_t* b) {
    asm volatile(
        "mma.sync.aligned.m16n8k16.row.col.f32.f16.f16.f32 "
        "{%0,%1,%2,%3}, {%4,%5,%6,%7}, {%8,%9}, {%0,%1,%2,%3};"
        : "+f"(d[0]), "+f"(d[1]), "+f"(d[2]), "+f"(d[3])
        : "r"(a[0]), "r"(a[1]), "r"(a[2]), "r"(a[3]), "r"(b[0]), "r"(b[1]));
}
__device__ __forceinline__ uint32_t pack_h2(float v0, float v1) {
    __half2 h;
    h.x = __float2half_rn(v0);
    h.y = __float2half_rn(v1);
    return *(uint32_t*)&h;
}

// ---------------------------------------------------------------------------
// Kernel 1: global average pool
// ---------------------------------------------------------------------------
__global__ void pool_kernel(const float* __restrict__ x) {
    const int ci = blockIdx.x;
    const int b  = blockIdx.y;
    const float* p = x + ((size_t)(b * CIN + ci)) * (HH * WW);
    float s = 0.f;
    for (int i = threadIdx.x; i < HH * WW; i += blockDim.x) s += p[i];
    __shared__ float red[32];
    #pragma unroll
    for (int o = 16; o; o >>= 1) s += __shfl_down_sync(0xffffffffu, s, o);
    if ((threadIdx.x & 31) == 0) red[threadIdx.x >> 5] = s;
    __syncthreads();
    if (threadIdx.x < 32) {
        s = (threadIdx.x < (blockDim.x >> 5)) ? red[threadIdx.x] : 0.f;
        #pragma unroll
        for (int o = 16; o; o >>= 1) s += __shfl_down_sync(0xffffffffu, s, o);
        if (threadIdx.x == 0) g_pooled[b * CIN + ci] = s * (1.0f / (HH * WW));
    }
}

// ---------------------------------------------------------------------------
// Kernel 2: attention MLP + softmax
// ---------------------------------------------------------------------------
__global__ void att_kernel(const float* __restrict__ w1,
                           const float* __restrict__ w2) {
    const int b = threadIdx.x;
    if (b >= BB) return;
    float pooled[CIN];
    #pragma unroll 8
    for (int i = 0; i < CIN; i++) pooled[i] = g_pooled[b * CIN + i];
    float l0 = 0.f, l1 = 0.f;
    for (int j = 0; j < HID; j++) {
        float h = 0.f;
        #pragma unroll 8
        for (int i = 0; i < CIN; i++) h += pooled[i] * w1[j * CIN + i];
        h = fmaxf(h, 0.f);
        l0 += h * w2[0 * HID + j];
        l1 += h * w2[1 * HID + j];
    }
    l0 *= (1.0f / TEMPR);
    l1 *= (1.0f / TEMPR);
    const float m  = fmaxf(l0, l1);
    const float e0 = __expf(l0 - m);
    const float e1 = __expf(l1 - m);
    const float inv = 1.0f / (e0 + e1);
    g_att[b * 2 + 0] = e0 * inv;
    g_att[b * 2 + 1] = e1 * inv;
}

// ---------------------------------------------------------------------------
// Kernel 3: mixed weight -> fp16
// ---------------------------------------------------------------------------
__global__ void wmix_kernel(const float* __restrict__ wc,
                            const float* __restrict__ we) {
    const int co = blockIdx.x;
    const int b  = blockIdx.y;
    const float a0 = g_att[2 * b], a1 = g_att[2 * b + 1];
    uint32_t* dst = (uint32_t*)(g_wh + ((size_t)b * COUT + co) * KDIM);
    const float* pc = wc + (size_t)co * KDIM;
    const float* pe = we + (size_t)co * KDIM;
    for (int k2 = threadIdx.x; k2 < KDIM / 2; k2 += blockDim.x) {
        const int k = k2 * 2;
        dst[k2] = pack_h2(a0 * pc[k] + a1 * pe[k],
                          a0 * pc[k + 1] + a1 * pe[k + 1]);
    }
}

// ---------------------------------------------------------------------------
// Kernel 4: im2col -> fp16.  Block = (oh, quarter, b).
// Slab row stride 65 floats: bank = (row + kw + 2*ow) mod 32 -> spread.
// ---------------------------------------------------------------------------
__global__ void __launch_bounds__(256) im2col_kernel(const float* __restrict__ x) {
    __shared__ float slab[SLABF];
    __shared__ __align__(16) int soff[QK];

    const int oh  = blockIdx.x;
    const int q   = blockIdx.y;
    const int b   = blockIdx.z;
    const int ci0 = q * CIQ;
    const int tid = threadIdx.x;
    const int wid = tid >> 5, lane = tid & 31;

    for (int j = tid; j < QK; j += 256) {
        const int cl = j / 25, t = j - cl * 25;
        const int kh = t / 5, kw = t - kh * 5;
        soff[j] = (cl * 5 + kh) * SROW + kw;
    }

    const float* xb = x + ((size_t)b * CIN + ci0) * (HH * WW) + (size_t)(oh * 2) * WW;
    for (int row = wid; row < CIQ * 5; row += 8) {
        const int cl = row / 5, kh = row - cl * 5;
        const float* src = xb + (size_t)cl * (HH * WW) + kh * WW;
        float* dstr = slab + row * SROW;
        if (lane < 63) dstr[lane] = src[lane];
        if (lane < 31) dstr[lane + 32] = src[lane + 32];
    }
    __syncthreads();

    uint32_t* dst0 = (uint32_t*)(g_xh + ((size_t)b * PPAD + oh * WO) * KDIM) + q * QK2;
    for (int idx = tid; idx < WO * QC4; idx += 256) {
        const int ow = idx / QC4;
        const int c4 = idx - ow * QC4;
        const int4 o0 = *(const int4*)&soff[c4 * 8];
        const int4 o1 = *(const int4*)&soff[c4 * 8 + 4];
        const float* sl = slab + ow * 2;
        uint4 v;
        v.x = pack_h2(sl[o0.x], sl[o0.y]);
        v.y = pack_h2(sl[o0.z], sl[o0.w]);
        v.z = pack_h2(sl[o1.x], sl[o1.y]);
        v.w = pack_h2(sl[o1.z], sl[o1.w]);
        *(uint4*)&dst0[(size_t)ow * (KDIM / 2) + c4 * 4] = v;
    }
}

// ---------------------------------------------------------------------------
// Kernel 5: fp16 mma.sync GEMM.  CTA = (b, co 128, p 96); 8 warps at 64x24.
// 4-stage cp.async, KSTEP=48; ldmatrix fragments; 2 CTAs/SM.
// ---------------------------------------------------------------------------
__global__ void __launch_bounds__(256, 2)
gemm_kernel(const float* __restrict__ cb, const float* __restrict__ eb,
            float* __restrict__ out)
{
    extern __shared__ uint32_t sm[];
    const int b   = blockIdx.y;
    const int ct  = blockIdx.x / NPT;         // 0..1
    const int pt  = blockIdx.x - ct * NPT;    // 0..9
    const int co0 = ct * MT;
    const int p0  = pt * NT;

    const int tid  = threadIdx.x;
    const int wid  = tid >> 5;
    const int lane = tid & 31;
    const int wm   = wid & 1;                 // warp M (2)
    const int wn   = wid >> 1;                // warp N (4)
    const int g    = lane >> 2;
    const int t    = lane & 3;

    const __half* gA = g_wh + ((size_t)b * COUT + co0) * KDIM;
    const __half* gB = g_xh + ((size_t)b * PPAD + p0) * KDIM;

    const uint32_t smbase = smem_u32(sm);

    // ldmatrix per-lane offsets (bytes within a stage)
    uint32_t aoff[4];
    #pragma unroll
    for (int m = 0; m < 4; m++) {
        const int row = wm * 64 + m * 16 + (lane & 15);
        aoff[m] = (uint32_t)(row * AROWU + (lane >> 4) * 4) * 4;
    }
    // B x4: n-frags 0,1 (rows wn*24 + 0..15)
    uint32_t boff4;
    {
        const int row = wn * 24 + ((lane >> 4) << 3) + (lane & 7);
        boff4 = (uint32_t)(ATILE_U + row * AROWU + ((lane >> 3) & 1) * 4) * 4;
    }
    // B x2: n-frag 2 (rows wn*24 + 16..23); lanes 0-7 khalf0, 8-15 khalf1
    uint32_t boff2;
    {
        const int row = wn * 24 + 16 + (lane & 7);
        boff2 = (uint32_t)(ATILE_U + row * AROWU + ((lane >> 3) & 1) * 4) * 4;
    }

    float acc[4][3][4];
    #pragma unroll
    for (int m = 0; m < 4; m++)
        #pragma unroll
        for (int n = 0; n < 3; n++)
            #pragma unroll
            for (int r = 0; r < 4; r++) acc[m][n][r] = 0.f;

    // ---- prologue: stages 0..2 ----
    #pragma unroll
    for (int s = 0; s < 3; s++) {
        const int k0 = s * KSTEP;
        const uint32_t ab = smbase + (uint32_t)(s * STAGE_U) * 4;
        const uint32_t bbs = ab + ATILE_U * 4;
        #pragma unroll
        for (int j = 0; j < 3; j++) {
            const int c = tid + 256 * j;
            const int r = c / 6, sg = c - r * 6;
            cp16(ab + (uint32_t)(r * AROWU + sg * 4) * 4, gA + (size_t)r * KDIM + k0 + sg * 8);
        }
        #pragma unroll
        for (int j = 0; j < 3; j++) {
            const int c = tid + 256 * j;
            if (c < BCHUNKS) {
                const int r = c / 6, sg = c - r * 6;
                cp16(bbs + (uint32_t)(r * AROWU + sg * 4) * 4, gB + (size_t)r * KDIM + k0 + sg * 8);
            }
        }
        cp_commit();
    }

    // ---- main loop ----
    for (int it = 0; it < NKIT; it++) {
        if (it + 3 < NKIT) {
            const int s = (it + 3) & 3;
            const int k0 = (it + 3) * KSTEP;
            const uint32_t ab = smbase + (uint32_t)(s * STAGE_U) * 4;
            const uint32_t bbs = ab + ATILE_U * 4;
            #pragma unroll
            for (int j = 0; j < 3; j++) {
                const int c = tid + 256 * j;
                const int r = c / 6, sg = c - r * 6;
                cp16(ab + (uint32_t)(r * AROWU + sg * 4) * 4, gA + (size_t)r * KDIM + k0 + sg * 8);
            }
            #pragma unroll
            for (int j = 0; j < 3; j++) {
                const int c = tid + 256 * j;
                if (c < BCHUNKS) {
                    const int r = c / 6, sg = c - r * 6;
                    cp16(bbs + (uint32_t)(r * AROWU + sg * 4) * 4, gB + (size_t)r * KDIM + k0 + sg * 8);
                }
            }
        }
        cp_commit();
        cp_wait3();
        __syncthreads();

        const uint32_t stoff = smbase + (uint32_t)((it & 3) * STAGE_U) * 4;

        #pragma unroll
        for (int kk = 0; kk < 3; kk++) {
            const uint32_t kb = stoff + kk * 32;
            uint32_t afr[4][4];
            #pragma unroll
            for (int m = 0; m < 4; m++)
                ldsm4(afr[m], kb + aoff[m]);
            uint32_t bfr[3][2];
            {
                uint32_t r4[4];
                ldsm4(r4, kb + boff4);
                bfr[0][0] = r4[0]; bfr[0][1] = r4[1];
                bfr[1][0] = r4[2]; bfr[1][1] = r4[3];
                ldsm2(bfr[2], kb + boff2);
            }
            #pragma unroll
            for (int m = 0; m < 4; m++)
                #pragma unroll
                for (int n = 0; n < 3; n++)
                    mma_f16(acc[m][n], afr[m], bfr[n]);
        }
        __syncthreads();
    }

    // ---- epilogue ----
    const float a0 = g_att[2 * b], a1 = g_att[2 * b + 1];
    #pragma unroll
    for (int m = 0; m < 4; m++) {
        const int co_lo = co0 + wm * 64 + m * 16 + g;
        const int co_hi = co_lo + 8;
        const float bias_lo = a0 * cb[co_lo] + a1 * eb[co_lo];
        const float bias_hi = a0 * cb[co_hi] + a1 * eb[co_hi];
        float* op_lo = out + ((size_t)b * COUT + co_lo) * PDIM;
        float* op_hi = out + ((size_t)b * COUT + co_hi) * PDIM;
        #pragma unroll
        for (int n = 0; n < 3; n++) {
            const int p = p0 + wn * 24 + n * 8 + t * 2;
            if (p < PDIM) {
                float2 v0 = make_float2(acc[m][n][0] + bias_lo, acc[m][n][1] + bias_lo);
                float2 v1 = make_float2(acc[m][n][2] + bias_hi, acc[m][n][3] + bias_hi);
                *(float2*)(op_lo + p) = v0;
                *(float2*)(op_hi + p) = v1;
            }
        }
    }
}

// ---------------------------------------------------------------------------
// Host launch
// ---------------------------------------------------------------------------
extern "C" void kernel_launch(void* const* d_in, const int* in_sizes, int n_in,
                              void* d_out, int out_size) {
    (void)in_sizes; (void)n_in; (void)out_size;
    const float* x  = (const float*)d_in[0];
    const float* wc = (const float*)d_in[1];
    const float* cb = (const float*)d_in[2];
    const float* we = (const float*)d_in[3];
    const float* eb = (const float*)d_in[4];
    const float* w1 = (const float*)d_in[5];
    const float* w2 = (const float*)d_in[6];
    float* out = (float*)d_out;

    static bool attr_set = false;
    if (!attr_set) {
        cudaFuncSetAttribute(gemm_kernel,
                             cudaFuncAttributeMaxDynamicSharedMemorySize, SMEM_B);
        attr_set = true;
    }

    pool_kernel<<<dim3(CIN, BB), 256>>>(x);
    att_kernel<<<1, 256>>>(w1, w2);
    wmix_kernel<<<dim3(COUT, BB), 256>>>(wc, we);
    im2col_kernel<<<dim3(HO, 4, BB), 256>>>(x);
    gemm_kernel<<<dim3(2 * NPT, BB), 256, SMEM_B>>>(cb, eb, out);
}

// round 12
// speedup vs baseline: 1.1888x; 1.0931x over previous
#include <cuda_runtime.h>
#include <cuda_fp16.h>
#include <cstdint>

// ---------------------------------------------------------------------------
// Problem constants
// ---------------------------------------------------------------------------
#define BB    128
#define CIN   96
#define HH    63
#define WW    63
#define COUT  256
#define HO    30
#define WO    30
#define HID   24
#define TEMPR 31.0f

#define KDIM  2400          // Cin * 25
#define PDIM  900           // Ho * Wo
#define PPAD  1024

// GEMM tiling: CTA 128(M) x 96(N), 8 warps at 64x24, fp16, KSTEP=48
#define KSTEP   48
#define NKIT    (KDIM / KSTEP)          // 50
#define MT      128
#define NT      96
#define NPT     10                      // p-tiles: 10 * 96 = 960
#define STAGES  4
#define AROWU   28                      // row stride in u32 = 112B
#define ATILE_U (MT * AROWU)            // 3584
#define BTILE_U (NT * AROWU)            // 2688
#define STAGE_U (ATILE_U + BTILE_U)     // 6272
#define SMEM_B  (STAGES * STAGE_U * 4)  // 100352 bytes -> 2 CTAs/SM
#define BCHUNKS (NT * 6)                // 576 cp.async chunks for B

// im2col: block = (ohp, quarter, b); 2 oh per block, 7-row slab
#define CIQ     24
#define QK      (CIQ * 25)              // 600 fp16 per quarter
#define QK2     (QK / 2)                // 300 u32
#define QC4     (QK2 / 4)               // 75 16B chunks per ow
#define OHB     2
#define SROWS   7                       // input rows per ci (2 oh + 5-tap)
#define SROW    65                      // slab row stride (bank spread)
#define SLABF   (CIQ * SROWS * SROW)    // 10920 floats

// ---------------------------------------------------------------------------
// Device scratch
// ---------------------------------------------------------------------------
__device__ float g_pooled[BB * CIN];
__device__ float g_att[BB * 2];
__device__ __align__(256) __half g_wh[(size_t)BB * COUT * KDIM];
__device__ __align__(256) __half g_xh[(size_t)BB * PPAD * KDIM];

// ---------------------------------------------------------------------------
// Helpers
// ---------------------------------------------------------------------------
__device__ __forceinline__ uint32_t smem_u32(const void* p) {
    uint32_t a;
    asm("{ .reg .u64 t; cvta.to.shared.u64 t, %1; cvt.u32.u64 %0, t; }"
        : "=r"(a) : "l"(p));
    return a;
}
__device__ __forceinline__ void cp16(uint32_t dst, const void* src) {
    asm volatile("cp.async.cg.shared.global [%0], [%1], 16;"
                 :: "r"(dst), "l"(src) : "memory");
}
__device__ __forceinline__ void cp_commit() {
    asm volatile("cp.async.commit_group;" ::: "memory");
}
__device__ __forceinline__ void cp_wait2() {
    asm volatile("cp.async.wait_group 2;" ::: "memory");
}
__device__ __forceinline__ void ldsm4(uint32_t* r, uint32_t addr) {
    asm volatile("ldmatrix.sync.aligned.m8n8.x4.shared.b16 {%0,%1,%2,%3}, [%4];"
                 : "=r"(r[0]), "=r"(r[1]), "=r"(r[2]), "=r"(r[3]) : "r"(addr));
}
__device__ __forceinline__ void ldsm2(uint32_t* r, uint32_t addr) {
    asm volatile("ldmatrix.sync.aligned.m8n8.x2.shared.b16 {%0,%1}, [%2];"
                 : "=r"(r[0]), "=r"(r[1]) : "r"(addr));
}
__device__ __forceinline__ void mma_f16(float* d, const uint32_t* a,
                                        const uint32_t* b) {
    asm volatile(
        "mma.sync.aligned.m16n8k16.row.col.f32.f16.f16.f32 "
        "{%0,%1,%2,%3}, {%4,%5,%6,%7}, {%8,%9}, {%0,%1,%2,%3};"
        : "+f"(d[0]), "+f"(d[1]), "+f"(d[2]), "+f"(d[3])
        : "r"(a[0]), "r"(a[1]), "r"(a[2]), "r"(a[3]), "r"(b[0]), "r"(b[1]));
}
__device__ __forceinline__ uint32_t pack_h2(float v0, float v1) {
    __half2 h;
    h.x = __float2half_rn(v0);
    h.y = __float2half_rn(v1);
    return *(uint32_t*)&h;
}

// ---------------------------------------------------------------------------
// Kernel 1: global average pool
// ---------------------------------------------------------------------------
__global__ void pool_kernel(const float* __restrict__ x) {
    const int ci = blockIdx.x;
    const int b  = blockIdx.y;
    const float* p = x + ((size_t)(b * CIN + ci)) * (HH * WW);
    float s = 0.f;
    for (int i = threadIdx.x; i < HH * WW; i += blockDim.x) s += p[i];
    __shared__ float red[32];
    #pragma unroll
    for (int o = 16; o; o >>= 1) s += __shfl_down_sync(0xffffffffu, s, o);
    if ((threadIdx.x & 31) == 0) red[threadIdx.x >> 5] = s;
    __syncthreads();
    if (threadIdx.x < 32) {
        s = (threadIdx.x < (blockDim.x >> 5)) ? red[threadIdx.x] : 0.f;
        #pragma unroll
        for (int o = 16; o; o >>= 1) s += __shfl_down_sync(0xffffffffu, s, o);
        if (threadIdx.x == 0) g_pooled[b * CIN + ci] = s * (1.0f / (HH * WW));
    }
}

// ---------------------------------------------------------------------------
// Kernel 2: attention MLP + softmax
// ---------------------------------------------------------------------------
__global__ void att_kernel(const float* __restrict__ w1,
                           const float* __restrict__ w2) {
    const int b = threadIdx.x;
    if (b >= BB) return;
    float pooled[CIN];
    #pragma unroll 8
    for (int i = 0; i < CIN; i++) pooled[i] = g_pooled[b * CIN + i];
    float l0 = 0.f, l1 = 0.f;
    for (int j = 0; j < HID; j++) {
        float h = 0.f;
        #pragma unroll 8
        for (int i = 0; i < CIN; i++) h += pooled[i] * w1[j * CIN + i];
        h = fmaxf(h, 0.f);
        l0 += h * w2[0 * HID + j];
        l1 += h * w2[1 * HID + j];
    }
    l0 *= (1.0f / TEMPR);
    l1 *= (1.0f / TEMPR);
    const float m  = fmaxf(l0, l1);
    const float e0 = __expf(l0 - m);
    const float e1 = __expf(l1 - m);
    const float inv = 1.0f / (e0 + e1);
    g_att[b * 2 + 0] = e0 * inv;
    g_att[b * 2 + 1] = e1 * inv;
}

// ---------------------------------------------------------------------------
// Kernel 3: mixed weight -> fp16
// ---------------------------------------------------------------------------
__global__ void wmix_kernel(const float* __restrict__ wc,
                            const float* __restrict__ we) {
    const int co = blockIdx.x;
    const int b  = blockIdx.y;
    const float a0 = g_att[2 * b], a1 = g_att[2 * b + 1];
    uint32_t* dst = (uint32_t*)(g_wh + ((size_t)b * COUT + co) * KDIM);
    const float* pc = wc + (size_t)co * KDIM;
    const float* pe = we + (size_t)co * KDIM;
    for (int k2 = threadIdx.x; k2 < KDIM / 2; k2 += blockDim.x) {
        const int k = k2 * 2;
        dst[k2] = pack_h2(a0 * pc[k] + a1 * pe[k],
                          a0 * pc[k + 1] + a1 * pe[k + 1]);
    }
}

// ---------------------------------------------------------------------------
// Kernel 4: im2col -> fp16.  Block = (ohp, quarter, b), 2 oh per block.
// Slab: 24ci x 7 rows x 63 cols (rows 4*ohp .. 4*ohp+6).
// ---------------------------------------------------------------------------
__global__ void __launch_bounds__(256) im2col_kernel(const float* __restrict__ x) {
    __shared__ float slab[SLABF];
    __shared__ __align__(16) int soff[QK];

    const int ohp = blockIdx.x;             // 0..14
    const int q   = blockIdx.y;
    const int b   = blockIdx.z;
    const int ci0 = q * CIQ;
    const int tid = threadIdx.x;
    const int wid = tid >> 5, lane = tid & 31;

    // LUT: j -> slab offset (row = cl*SROWS + kh)
    for (int j = tid; j < QK; j += 256) {
        const int cl = j / 25, t = j - cl * 25;
        const int kh = t / 5, kw = t - kh * 5;
        soff[j] = (cl * SROWS + kh) * SROW + kw;
    }

    // stage slab: CIQ*7 = 168 rows of 63 floats; input row = 4*ohp + rr (<= 62)
    const float* xb = x + ((size_t)b * CIN + ci0) * (HH * WW) + (size_t)(ohp * 4) * WW;
    for (int row = wid; row < CIQ * SROWS; row += 8) {
        const int cl = row / SROWS, rr = row - cl * SROWS;
        const float* src = xb + (size_t)cl * (HH * WW) + rr * WW;
        float* dstr = slab + row * SROW;
        if (lane < 63) dstr[lane] = src[lane];
        if (lane < 31) dstr[lane + 32] = src[lane + 32];
    }
    __syncthreads();

    // emit: 2 oh x 30 ow x 75 chunks = 4500
    uint32_t* dst0 = (uint32_t*)(g_xh + ((size_t)b * PPAD + ohp * OHB * WO) * KDIM)
                     + q * QK2;
    for (int idx = tid; idx < OHB * WO * QC4; idx += 256) {
        const int owc = idx / QC4;          // 0..59
        const int c4  = idx - owc * QC4;
        const int dl  = owc / WO;           // 0..1 (which oh)
        const int ow  = owc - dl * WO;
        const int4 o0 = *(const int4*)&soff[c4 * 8];
        const int4 o1 = *(const int4*)&soff[c4 * 8 + 4];
        const float* sl = slab + dl * 2 * SROW + ow * 2;
        uint4 v;
        v.x = pack_h2(sl[o0.x], sl[o0.y]);
        v.y = pack_h2(sl[o0.z], sl[o0.w]);
        v.z = pack_h2(sl[o1.x], sl[o1.y]);
        v.w = pack_h2(sl[o1.z], sl[o1.w]);
        *(uint4*)&dst0[(size_t)owc * (KDIM / 2) + c4 * 4] = v;
    }
}

// ---------------------------------------------------------------------------
// Kernel 5: fp16 mma.sync GEMM.  CTA = (b, co 128, p 96); 8 warps at 64x24.
// 4-stage cp.async, KSTEP=48, single barrier per iteration, 2 CTAs/SM.
// ---------------------------------------------------------------------------
__global__ void __launch_bounds__(256, 2)
gemm_kernel(const float* __restrict__ cb, const float* __restrict__ eb,
            float* __restrict__ out)
{
    extern __shared__ uint32_t sm[];
    const int b   = blockIdx.y;
    const int ct  = blockIdx.x / NPT;
    const int pt  = blockIdx.x - ct * NPT;
    const int co0 = ct * MT;
    const int p0  = pt * NT;

    const int tid  = threadIdx.x;
    const int wid  = tid >> 5;
    const int lane = tid & 31;
    const int wm   = wid & 1;
    const int wn   = wid >> 1;
    const int g    = lane >> 2;
    const int t    = lane & 3;

    const __half* gA = g_wh + ((size_t)b * COUT + co0) * KDIM;
    const __half* gB = g_xh + ((size_t)b * PPAD + p0) * KDIM;

    const uint32_t smbase = smem_u32(sm);

    uint32_t aoff[4];
    #pragma unroll
    for (int m = 0; m < 4; m++) {
        const int row = wm * 64 + m * 16 + (lane & 15);
        aoff[m] = (uint32_t)(row * AROWU + (lane >> 4) * 4) * 4;
    }
    uint32_t boff4;
    {
        const int row = wn * 24 + ((lane >> 4) << 3) + (lane & 7);
        boff4 = (uint32_t)(ATILE_U + row * AROWU + ((lane >> 3) & 1) * 4) * 4;
    }
    uint32_t boff2;
    {
        const int row = wn * 24 + 16 + (lane & 7);
        boff2 = (uint32_t)(ATILE_U + row * AROWU + ((lane >> 3) & 1) * 4) * 4;
    }

    float acc[4][3][4];
    #pragma unroll
    for (int m = 0; m < 4; m++)
        #pragma unroll
        for (int n = 0; n < 3; n++)
            #pragma unroll
            for (int r = 0; r < 4; r++) acc[m][n][r] = 0.f;

    // ---- prologue: stages 0..2 ----
    #pragma unroll
    for (int s = 0; s < 3; s++) {
        const int k0 = s * KSTEP;
        const uint32_t ab = smbase + (uint32_t)(s * STAGE_U) * 4;
        const uint32_t bbs = ab + ATILE_U * 4;
        #pragma unroll
        for (int j = 0; j < 3; j++) {
            const int c = tid + 256 * j;
            const int r = c / 6, sg = c - r * 6;
            cp16(ab + (uint32_t)(r * AROWU + sg * 4) * 4, gA + (size_t)r * KDIM + k0 + sg * 8);
        }
        #pragma unroll
        for (int j = 0; j < 3; j++) {
            const int c = tid + 256 * j;
            if (c < BCHUNKS) {
                const int r = c / 6, sg = c - r * 6;
                cp16(bbs + (uint32_t)(r * AROWU + sg * 4) * 4, gB + (size_t)r * KDIM + k0 + sg * 8);
            }
        }
        cp_commit();
    }

    // ---- main loop: single barrier per iteration ----
    for (int it = 0; it < NKIT; it++) {
        cp_wait2();          // stage it resident (<=2 younger groups outstanding)
        __syncthreads();     // all threads done reading stage (it-1)&3

        if (it + 3 < NKIT) { // refill stage (it+3)&3 == (it-1)&3
            const int s = (it + 3) & 3;
            const int k0 = (it + 3) * KSTEP;
            const uint32_t ab = smbase + (uint32_t)(s * STAGE_U) * 4;
            const uint32_t bbs = ab + ATILE_U * 4;
            #pragma unroll
            for (int j = 0; j < 3; j++) {
                const int c = tid + 256 * j;
                const int r = c / 6, sg = c - r * 6;
                cp16(ab + (uint32_t)(r * AROWU + sg * 4) * 4, gA + (size_t)r * KDIM + k0 + sg * 8);
            }
            #pragma unroll
            for (int j = 0; j < 3; j++) {
                const int c = tid + 256 * j;
                if (c < BCHUNKS) {
                    const int r = c / 6, sg = c - r * 6;
                    cp16(bbs + (uint32_t)(r * AROWU + sg * 4) * 4, gB + (size_t)r * KDIM + k0 + sg * 8);
                }
            }
        }
        cp_commit();

        const uint32_t stoff = smbase + (uint32_t)((it & 3) * STAGE_U) * 4;

        #pragma unroll
        for (int kk = 0; kk < 3; kk++) {
            const uint32_t kb = stoff + kk * 32;
            uint32_t afr[4][4];
            #pragma unroll
            for (int m = 0; m < 4; m++)
                ldsm4(afr[m], kb + aoff[m]);
            uint32_t bfr[3][2];
            {
                uint32_t r4[4];
                ldsm4(r4, kb + boff4);
                bfr[0][0] = r4[0]; bfr[0][1] = r4[1];
                bfr[1][0] = r4[2]; bfr[1][1] = r4[3];
                ldsm2(bfr[2], kb + boff2);
            }
            #pragma unroll
            for (int m = 0; m < 4; m++)
                #pragma unroll
                for (int n = 0; n < 3; n++)
                    mma_f16(acc[m][n], afr[m], bfr[n]);
        }
    }

    // ---- epilogue ----
    const float a0 = g_att[2 * b], a1 = g_att[2 * b + 1];
    #pragma unroll
    for (int m = 0; m < 4; m++) {
        const int co_lo = co0 + wm * 64 + m * 16 + g;
        const int co_hi = co_lo + 8;
        const float bias_lo = a0 * cb[co_lo] + a1 * eb[co_lo];
        const float bias_hi = a0 * cb[co_hi] + a1 * eb[co_hi];
        float* op_lo = out + ((size_t)b * COUT + co_lo) * PDIM;
        float* op_hi = out + ((size_t)b * COUT + co_hi) * PDIM;
        #pragma unroll
        for (int n = 0; n < 3; n++) {
            const int p = p0 + wn * 24 + n * 8 + t * 2;
            if (p < PDIM) {
                float2 v0 = make_float2(acc[m][n][0] + bias_lo, acc[m][n][1] + bias_lo);
                float2 v1 = make_float2(acc[m][n][2] + bias_hi, acc[m][n][3] + bias_hi);
                *(float2*)(op_lo + p) = v0;
                *(float2*)(op_hi + p) = v1;
            }
        }
    }
}

// ---------------------------------------------------------------------------
// Host launch
// ---------------------------------------------------------------------------
extern "C" void kernel_launch(void* const* d_in, const int* in_sizes, int n_in,
                              void* d_out, int out_size) {
    (void)in_sizes; (void)n_in; (void)out_size;
    const float* x  = (const float*)d_in[0];
    const float* wc = (const float*)d_in[1];
    const float* cb = (const float*)d_in[2];
    const float* we = (const float*)d_in[3];
    const float* eb = (const float*)d_in[4];
    const float* w1 = (const float*)d_in[5];
    const float* w2 = (const float*)d_in[6];
    float* out = (float*)d_out;

    static bool attr_set = false;
    if (!attr_set) {
        cudaFuncSetAttribute(gemm_kernel,
                             cudaFuncAttributeMaxDynamicSharedMemorySize, SMEM_B);
        attr_set = true;
    }

    pool_kernel<<<dim3(CIN, BB), 256>>>(x);
    att_kernel<<<1, 256>>>(w1, w2);
    wmix_kernel<<<dim3(COUT, BB), 256>>>(wc, we);
    im2col_kernel<<<dim3(HO / OHB, 4, BB), 256>>>(x);
    gemm_kernel<<<dim3(2 * NPT, BB), 256, SMEM_B>>>(cb, eb, out);
}

// round 13
// speedup vs baseline: 1.1989x; 1.0084x over previous
#include <cuda_runtime.h>
#include <cuda_fp16.h>
#include <cstdint>

// ---------------------------------------------------------------------------
// Problem constants
// ---------------------------------------------------------------------------
#define BB    128
#define CIN   96
#define HH    63
#define WW    63
#define COUT  256
#define HO    30
#define WO    30
#define HID   24
#define TEMPR 31.0f

#define KDIM  2400          // Cin * 25
#define PDIM  900           // Ho * Wo
#define PPAD  1024

// GEMM tiling: CTA 128(M) x 96(N), 8 warps at 64x24, fp16, KSTEP=48
#define KSTEP   48
#define NKIT    (KDIM / KSTEP)          // 50
#define MT      128
#define NT      96
#define NPT     10                      // p-tiles: 10 * 96 = 960
#define STAGES  4
#define AROWU   28                      // row stride in u32 = 112B
#define ATILE_U (MT * AROWU)            // 3584
#define BTILE_U (NT * AROWU)            // 2688
#define STAGE_U (ATILE_U + BTILE_U)     // 6272
#define SMEM_B  (STAGES * STAGE_U * 4)  // 100352 bytes -> 2 CTAs/SM
#define BCHUNKS (NT * 6)                // 576 cp.async chunks for B

// im2col: block = (ohp, quarter, b); 2 oh per block, 7-row slab
#define CIQ     24
#define QK      (CIQ * 25)              // 600 fp16 per quarter
#define QK2     (QK / 2)                // 300 u32
#define QC4     (QK2 / 4)               // 75 16B chunks per ow
#define OHB     2
#define SROWS   7                       // input rows per ci (2 oh + 5-tap)
#define SROW    65                      // slab row stride (bank spread)
#define SLABF   (CIQ * SROWS * SROW)    // 10920 floats

// ---------------------------------------------------------------------------
// Device scratch
// ---------------------------------------------------------------------------
__device__ float g_pooled[BB * CIN];
__device__ float g_att[BB * 2];
__device__ __align__(256) __half g_wh[(size_t)BB * COUT * KDIM];
__device__ __align__(256) __half g_xh[(size_t)BB * PPAD * KDIM];

// ---------------------------------------------------------------------------
// Helpers
// ---------------------------------------------------------------------------
__device__ __forceinline__ uint32_t smem_u32(const void* p) {
    uint32_t a;
    asm("{ .reg .u64 t; cvta.to.shared.u64 t, %1; cvt.u32.u64 %0, t; }"
        : "=r"(a) : "l"(p));
    return a;
}
__device__ __forceinline__ void cp16(uint32_t dst, const void* src) {
    asm volatile("cp.async.cg.shared.global [%0], [%1], 16;"
                 :: "r"(dst), "l"(src) : "memory");
}
__device__ __forceinline__ void cp_commit() {
    asm volatile("cp.async.commit_group;" ::: "memory");
}
__device__ __forceinline__ void cp_wait2() {
    asm volatile("cp.async.wait_group 2;" ::: "memory");
}
__device__ __forceinline__ void ldsm4(uint32_t* r, uint32_t addr) {
    asm volatile("ldmatrix.sync.aligned.m8n8.x4.shared.b16 {%0,%1,%2,%3}, [%4];"
                 : "=r"(r[0]), "=r"(r[1]), "=r"(r[2]), "=r"(r[3]) : "r"(addr));
}
__device__ __forceinline__ void ldsm2(uint32_t* r, uint32_t addr) {
    asm volatile("ldmatrix.sync.aligned.m8n8.x2.shared.b16 {%0,%1}, [%2];"
                 : "=r"(r[0]), "=r"(r[1]) : "r"(addr));
}
__device__ __forceinline__ void mma_f16(float* d, const uint32_t* a,
                                        const uint32_t* b) {
    asm volatile(
        "mma.sync.aligned.m16n8k16.row.col.f32.f16.f16.f32 "
        "{%0,%1,%2,%3}, {%4,%5,%6,%7}, {%8,%9}, {%0,%1,%2,%3};"
        : "+f"(d[0]), "+f"(d[1]), "+f"(d[2]), "+f"(d[3])
        : "r"(a[0]), "r"(a[1]), "r"(a[2]), "r"(a[3]), "r"(b[0]), "r"(b[1]));
}
__device__ __forceinline__ uint32_t pack_h2(float v0, float v1) {
    __half2 h;
    h.x = __float2half_rn(v0);
    h.y = __float2half_rn(v1);
    return *(uint32_t*)&h;
}

// ---------------------------------------------------------------------------
// Kernel 1: global average pool
// ---------------------------------------------------------------------------
__global__ void pool_kernel(const float* __restrict__ x) {
    const int ci = blockIdx.x;
    const int b  = blockIdx.y;
    const float* p = x + ((size_t)(b * CIN + ci)) * (HH * WW);
    float s = 0.f;
    for (int i = threadIdx.x; i < HH * WW; i += blockDim.x) s += p[i];
    __shared__ float red[32];
    #pragma unroll
    for (int o = 16; o; o >>= 1) s += __shfl_down_sync(0xffffffffu, s, o);
    if ((threadIdx.x & 31) == 0) red[threadIdx.x >> 5] = s;
    __syncthreads();
    if (threadIdx.x < 32) {
        s = (threadIdx.x < (blockDim.x >> 5)) ? red[threadIdx.x] : 0.f;
        #pragma unroll
        for (int o = 16; o; o >>= 1) s += __shfl_down_sync(0xffffffffu, s, o);
        if (threadIdx.x == 0) g_pooled[b * CIN + ci] = s * (1.0f / (HH * WW));
    }
}

// ---------------------------------------------------------------------------
// Kernel 2: attention MLP + softmax
// ---------------------------------------------------------------------------
__global__ void att_kernel(const float* __restrict__ w1,
                           const float* __restrict__ w2) {
    const int b = threadIdx.x;
    if (b >= BB) return;
    float pooled[CIN];
    #pragma unroll 8
    for (int i = 0; i < CIN; i++) pooled[i] = g_pooled[b * CIN + i];
    float l0 = 0.f, l1 = 0.f;
    for (int j = 0; j < HID; j++) {
        float h = 0.f;
        #pragma unroll 8
        for (int i = 0; i < CIN; i++) h += pooled[i] * w1[j * CIN + i];
        h = fmaxf(h, 0.f);
        l0 += h * w2[0 * HID + j];
        l1 += h * w2[1 * HID + j];
    }
    l0 *= (1.0f / TEMPR);
    l1 *= (1.0f / TEMPR);
    const float m  = fmaxf(l0, l1);
    const float e0 = __expf(l0 - m);
    const float e1 = __expf(l1 - m);
    const float inv = 1.0f / (e0 + e1);
    g_att[b * 2 + 0] = e0 * inv;
    g_att[b * 2 + 1] = e1 * inv;
}

// ---------------------------------------------------------------------------
// Kernel 3: mixed weight -> fp16
// ---------------------------------------------------------------------------
__global__ void wmix_kernel(const float* __restrict__ wc,
                            const float* __restrict__ we) {
    const int co = blockIdx.x;
    const int b  = blockIdx.y;
    const float a0 = g_att[2 * b], a1 = g_att[2 * b + 1];
    uint32_t* dst = (uint32_t*)(g_wh + ((size_t)b * COUT + co) * KDIM);
    const float* pc = wc + (size_t)co * KDIM;
    const float* pe = we + (size_t)co * KDIM;
    for (int k2 = threadIdx.x; k2 < KDIM / 2; k2 += blockDim.x) {
        const int k = k2 * 2;
        dst[k2] = pack_h2(a0 * pc[k] + a1 * pe[k],
                          a0 * pc[k + 1] + a1 * pe[k + 1]);
    }
}

// ---------------------------------------------------------------------------
// Kernel 4: im2col -> fp16.  Block = (ohp, quarter, b), 2 oh per block.
// ---------------------------------------------------------------------------
__global__ void __launch_bounds__(256) im2col_kernel(const float* __restrict__ x) {
    __shared__ float slab[SLABF];
    __shared__ __align__(16) int soff[QK];

    const int ohp = blockIdx.x;
    const int q   = blockIdx.y;
    const int b   = blockIdx.z;
    const int ci0 = q * CIQ;
    const int tid = threadIdx.x;
    const int wid = tid >> 5, lane = tid & 31;

    for (int j = tid; j < QK; j += 256) {
        const int cl = j / 25, t = j - cl * 25;
        const int kh = t / 5, kw = t - kh * 5;
        soff[j] = (cl * SROWS + kh) * SROW + kw;
    }

    const float* xb = x + ((size_t)b * CIN + ci0) * (HH * WW) + (size_t)(ohp * 4) * WW;
    for (int row = wid; row < CIQ * SROWS; row += 8) {
        const int cl = row / SROWS, rr = row - cl * SROWS;
        const float* src = xb + (size_t)cl * (HH * WW) + rr * WW;
        float* dstr = slab + row * SROW;
        if (lane < 63) dstr[lane] = src[lane];
        if (lane < 31) dstr[lane + 32] = src[lane + 32];
    }
    __syncthreads();

    uint32_t* dst0 = (uint32_t*)(g_xh + ((size_t)b * PPAD + ohp * OHB * WO) * KDIM)
                     + q * QK2;
    for (int idx = tid; idx < OHB * WO * QC4; idx += 256) {
        const int owc = idx / QC4;
        const int c4  = idx - owc * QC4;
        const int dl  = owc / WO;
        const int ow  = owc - dl * WO;
        const int4 o0 = *(const int4*)&soff[c4 * 8];
        const int4 o1 = *(const int4*)&soff[c4 * 8 + 4];
        const float* sl = slab + dl * 2 * SROW + ow * 2;
        uint4 v;
        v.x = pack_h2(sl[o0.x], sl[o0.y]);
        v.y = pack_h2(sl[o0.z], sl[o0.w]);
        v.z = pack_h2(sl[o1.x], sl[o1.y]);
        v.w = pack_h2(sl[o1.z], sl[o1.w]);
        *(uint4*)&dst0[(size_t)owc * (KDIM / 2) + c4 * 4] = v;
    }
}

// ---------------------------------------------------------------------------
// Kernel 5: fp16 mma.sync GEMM.  CTA = (b, co 128, p 96); 8 warps at 64x24.
// 4-stage cp.async, KSTEP=48, single barrier per iteration, 2 CTAs/SM.
// ---------------------------------------------------------------------------
__global__ void __launch_bounds__(256, 2)
gemm_kernel(const float* __restrict__ cb, const float* __restrict__ eb,
            float* __restrict__ out)
{
    extern __shared__ uint32_t sm[];
    const int b   = blockIdx.y;
    const int ct  = blockIdx.x / NPT;
    const int pt  = blockIdx.x - ct * NPT;
    const int co0 = ct * MT;
    const int p0  = pt * NT;

    const int tid  = threadIdx.x;
    const int wid  = tid >> 5;
    const int lane = tid & 31;
    const int wm   = wid & 1;
    const int wn   = wid >> 1;
    const int g    = lane >> 2;
    const int t    = lane & 3;

    const __half* gA = g_wh + ((size_t)b * COUT + co0) * KDIM;
    const __half* gB = g_xh + ((size_t)b * PPAD + p0) * KDIM;

    const uint32_t smbase = smem_u32(sm);

    uint32_t aoff[4];
    #pragma unroll
    for (int m = 0; m < 4; m++) {
        const int row = wm * 64 + m * 16 + (lane & 15);
        aoff[m] = (uint32_t)(row * AROWU + (lane >> 4) * 4) * 4;
    }
    uint32_t boff4;
    {
        const int row = wn * 24 + ((lane >> 4) << 3) + (lane & 7);
        boff4 = (uint32_t)(ATILE_U + row * AROWU + ((lane >> 3) & 1) * 4) * 4;
    }
    uint32_t boff2;
    {
        const int row = wn * 24 + 16 + (lane & 7);
        boff2 = (uint32_t)(ATILE_U + row * AROWU + ((lane >> 3) & 1) * 4) * 4;
    }

    float acc[4][3][4];
    #pragma unroll
    for (int m = 0; m < 4; m++)
        #pragma unroll
        for (int n = 0; n < 3; n++)
            #pragma unroll
            for (int r = 0; r < 4; r++) acc[m][n][r] = 0.f;

    // ---- prologue: stages 0..2 ----
    #pragma unroll
    for (int s = 0; s < 3; s++) {
        const int k0 = s * KSTEP;
        const uint32_t ab = smbase + (uint32_t)(s * STAGE_U) * 4;
        const uint32_t bbs = ab + ATILE_U * 4;
        #pragma unroll
        for (int j = 0; j < 3; j++) {
            const int c = tid + 256 * j;
            const int r = c / 6, sg = c - r * 6;
            cp16(ab + (uint32_t)(r * AROWU + sg * 4) * 4, gA + (size_t)r * KDIM + k0 + sg * 8);
        }
        #pragma unroll
        for (int j = 0; j < 3; j++) {
            const int c = tid + 256 * j;
            if (c < BCHUNKS) {
                const int r = c / 6, sg = c - r * 6;
                cp16(bbs + (uint32_t)(r * AROWU + sg * 4) * 4, gB + (size_t)r * KDIM + k0 + sg * 8);
            }
        }
        cp_commit();
    }

    // ---- main loop: single barrier per iteration ----
    for (int it = 0; it < NKIT; it++) {
        cp_wait2();
        __syncthreads();

        if (it + 3 < NKIT) {
            const int s = (it + 3) & 3;
            const int k0 = (it + 3) * KSTEP;
            const uint32_t ab = smbase + (uint32_t)(s * STAGE_U) * 4;
            const uint32_t bbs = ab + ATILE_U * 4;
            #pragma unroll
            for (int j = 0; j < 3; j++) {
                const int c = tid + 256 * j;
                const int r = c / 6, sg = c - r * 6;
                cp16(ab + (uint32_t)(r * AROWU + sg * 4) * 4, gA + (size_t)r * KDIM + k0 + sg * 8);
            }
            #pragma unroll
            for (int j = 0; j < 3; j++) {
                const int c = tid + 256 * j;
                if (c < BCHUNKS) {
                    const int r = c / 6, sg = c - r * 6;
                    cp16(bbs + (uint32_t)(r * AROWU + sg * 4) * 4, gB + (size_t)r * KDIM + k0 + sg * 8);
                }
            }
        }
        cp_commit();

        const uint32_t stoff = smbase + (uint32_t)((it & 3) * STAGE_U) * 4;

        #pragma unroll
        for (int kk = 0; kk < 3; kk++) {
            const uint32_t kb = stoff + kk * 32;
            uint32_t afr[4][4];
            #pragma unroll
            for (int m = 0; m < 4; m++)
                ldsm4(afr[m], kb + aoff[m]);
            uint32_t bfr[3][2];
            {
                uint32_t r4[4];
                ldsm4(r4, kb + boff4);
                bfr[0][0] = r4[0]; bfr[0][1] = r4[1];
                bfr[1][0] = r4[2]; bfr[1][1] = r4[3];
                ldsm2(bfr[2], kb + boff2);
            }
            #pragma unroll
            for (int m = 0; m < 4; m++)
                #pragma unroll
                for (int n = 0; n < 3; n++)
                    mma_f16(acc[m][n], afr[m], bfr[n]);
        }
    }

    // ---- epilogue ----
    const float a0 = g_att[2 * b], a1 = g_att[2 * b + 1];
    #pragma unroll
    for (int m = 0; m < 4; m++) {
        const int co_lo = co0 + wm * 64 + m * 16 + g;
        const int co_hi = co_lo + 8;
        const float bias_lo = a0 * cb[co_lo] + a1 * eb[co_lo];
        const float bias_hi = a0 * cb[co_hi] + a1 * eb[co_hi];
        float* op_lo = out + ((size_t)b * COUT + co_lo) * PDIM;
        float* op_hi = out + ((size_t)b * COUT + co_hi) * PDIM;
        #pragma unroll
        for (int n = 0; n < 3; n++) {
            const int p = p0 + wn * 24 + n * 8 + t * 2;
            if (p < PDIM) {
                float2 v0 = make_float2(acc[m][n][0] + bias_lo, acc[m][n][1] + bias_lo);
                float2 v1 = make_float2(acc[m][n][2] + bias_hi, acc[m][n][3] + bias_hi);
                *(float2*)(op_lo + p) = v0;
                *(float2*)(op_hi + p) = v1;
            }
        }
    }
}

// ---------------------------------------------------------------------------
// Host launch: fork attention branch onto a side stream so it overlaps im2col.
// Streams/events are created once at the first (uncaptured) call; during
// capture only launches + event record/wait are issued (all graph-legal).
// ---------------------------------------------------------------------------
extern "C" void kernel_launch(void* const* d_in, const int* in_sizes, int n_in,
                              void* d_out, int out_size) {
    (void)in_sizes; (void)n_in; (void)out_size;
    const float* x  = (const float*)d_in[0];
    const float* wc = (const float*)d_in[1];
    const float* cb = (const float*)d_in[2];
    const float* we = (const float*)d_in[3];
    const float* eb = (const float*)d_in[4];
    const float* w1 = (const float*)d_in[5];
    const float* w2 = (const float*)d_in[6];
    float* out = (float*)d_out;

    static cudaStream_t s2 = nullptr;
    static cudaEvent_t ev_root = nullptr, ev_join = nullptr;
    if (s2 == nullptr) {
        cudaStreamCreateWithFlags(&s2, cudaStreamNonBlocking);
        cudaEventCreateWithFlags(&ev_root, cudaEventDisableTiming);
        cudaEventCreateWithFlags(&ev_join, cudaEventDisableTiming);
        cudaFuncSetAttribute(gemm_kernel,
                             cudaFuncAttributeMaxDynamicSharedMemorySize, SMEM_B);
    }

    // fork: side stream runs the attention/weight-mix chain
    cudaEventRecord(ev_root, 0);
    cudaStreamWaitEvent(s2, ev_root, 0);

    pool_kernel<<<dim3(CIN, BB), 256, 0, s2>>>(x);
    att_kernel<<<1, 256, 0, s2>>>(w1, w2);
    wmix_kernel<<<dim3(COUT, BB), 256, 0, s2>>>(wc, we);

    // main stream runs the long pole
    im2col_kernel<<<dim3(HO / OHB, 4, BB), 256>>>(x);

    // join: gemm needs both branches
    cudaEventRecord(ev_join, s2);
    cudaStreamWaitEvent(0, ev_join, 0);
    gemm_kernel<<<dim3(2 * NPT, BB), 256, SMEM_B>>>(cb, eb, out);
}